// round 1
// baseline (speedup 1.0000x reference)
#include <cuda_runtime.h>
#include <cstdint>
#include <cstddef>

#define NB 16
#define NA 1024
#define C_DIM 512
#define NH 8
#define D_DIM 64

// ---------------- device scratch (static, no allocation) ----------------
__device__ float g_Q[NB * NH * NA * D_DIM];   // [b][h][i][d]
__device__ float g_K[NB * NH * NA * D_DIM];
__device__ float g_V[NB * NH * NA * D_DIM];
__device__ float g_S[(size_t)NB * NH * NA * NA]; // raw masked scores
__device__ float g_m[NB * NH * NA];           // per-row running max
__device__ float g_l[NB * NH * NA];           // per-row sum exp
__device__ int   g_maskType;                  // 0=u8, 1=i32, 2=f32

// ---------------- kernel 0: detect mask dtype ----------------
__global__ void detect_mask_kernel(const unsigned int* __restrict__ mw) {
    int gt1 = 0, f32 = 0;
    for (int t = threadIdx.x; t < 4096; t += 256) {
        unsigned v = mw[t];
        if (v == 0x3F800000u) f32 = 1;
        else if (v > 1u) gt1 = 1;
    }
    gt1 = __syncthreads_or(gt1);
    f32 = __syncthreads_or(f32);
    if (threadIdx.x == 0) g_maskType = f32 ? 2 : (gt1 ? 0 : 1);
}

// ---------------- kernel 1: QKV projection GEMM ----------------
// Y = x(M=16384,K=512) @ W(N=512,K=512)^T, written as [b][h][i][d]
// Block 128x128, BK=16, 256 threads, 8x8 micro-tile.
__global__ __launch_bounds__(256)
void qkv_gemm_kernel(const float* __restrict__ x,
                     const float* __restrict__ Wq,
                     const float* __restrict__ Wk,
                     const float* __restrict__ Wv) {
    __shared__ float As[16][132];
    __shared__ float Bs[16][132];

    const int z = blockIdx.z;
    const float* __restrict__ W = (z == 0) ? Wq : (z == 1) ? Wk : Wv;
    float* __restrict__ outp = (z == 0) ? g_Q : (z == 1) ? g_K : g_V;

    const int mBase = blockIdx.x * 128;
    const int nBase = blockIdx.y * 128;
    const int tx = threadIdx.x, ty = threadIdx.y;
    const int tid = ty * 16 + tx;

    const int lm = tid >> 2;          // 0..63
    const int lk = (tid & 3) * 4;     // 0,4,8,12

    float acc[8][8];
#pragma unroll
    for (int i = 0; i < 8; i++)
#pragma unroll
        for (int j = 0; j < 8; j++) acc[i][j] = 0.0f;

    for (int k0 = 0; k0 < C_DIM; k0 += 16) {
        float4 a0 = *(const float4*)&x[(size_t)(mBase + lm) * C_DIM + k0 + lk];
        float4 a1 = *(const float4*)&x[(size_t)(mBase + lm + 64) * C_DIM + k0 + lk];
        float4 b0 = *(const float4*)&W[(size_t)(nBase + lm) * C_DIM + k0 + lk];
        float4 b1 = *(const float4*)&W[(size_t)(nBase + lm + 64) * C_DIM + k0 + lk];

        __syncthreads();
        As[lk + 0][lm] = a0.x; As[lk + 1][lm] = a0.y; As[lk + 2][lm] = a0.z; As[lk + 3][lm] = a0.w;
        As[lk + 0][lm + 64] = a1.x; As[lk + 1][lm + 64] = a1.y; As[lk + 2][lm + 64] = a1.z; As[lk + 3][lm + 64] = a1.w;
        Bs[lk + 0][lm] = b0.x; Bs[lk + 1][lm] = b0.y; Bs[lk + 2][lm] = b0.z; Bs[lk + 3][lm] = b0.w;
        Bs[lk + 0][lm + 64] = b1.x; Bs[lk + 1][lm + 64] = b1.y; Bs[lk + 2][lm + 64] = b1.z; Bs[lk + 3][lm + 64] = b1.w;
        __syncthreads();

#pragma unroll
        for (int kk = 0; kk < 16; kk++) {
            float a[8], b[8];
            *(float4*)&a[0] = *(const float4*)&As[kk][ty * 4];
            *(float4*)&a[4] = *(const float4*)&As[kk][ty * 4 + 64];
            *(float4*)&b[0] = *(const float4*)&Bs[kk][tx * 4];
            *(float4*)&b[4] = *(const float4*)&Bs[kk][tx * 4 + 64];
#pragma unroll
            for (int i = 0; i < 8; i++)
#pragma unroll
                for (int j = 0; j < 8; j++) acc[i][j] += a[i] * b[j];
        }
    }

    // epilogue: n -> (h,d); m -> (b,i); layout [b][h][i][d]
#pragma unroll
    for (int gi = 0; gi < 2; gi++) {
#pragma unroll
        for (int r = 0; r < 4; r++) {
            int m = mBase + ty * 4 + r + gi * 64;
            int b = m >> 10, i = m & 1023;
#pragma unroll
            for (int gj = 0; gj < 2; gj++) {
                int n0 = nBase + tx * 4 + gj * 64;
                int h = n0 >> 6, d = n0 & 63;
                float4 v;
                v.x = acc[gi * 4 + r][gj * 4 + 0];
                v.y = acc[gi * 4 + r][gj * 4 + 1];
                v.z = acc[gi * 4 + r][gj * 4 + 2];
                v.w = acc[gi * 4 + r][gj * 4 + 3];
                *(float4*)&outp[(((size_t)(b * NH + h) * NA + i) * D_DIM) + d] = v;
            }
        }
    }
}

// ---------------- kernel 2: scores = QK^T/TP + adj, masked; online (m,l) ----------------
// grid (NA/64, NH, NB), block (16,16). Each block: 64 query rows x full NA.
__global__ __launch_bounds__(256)
void scores_kernel(const float* __restrict__ adj, const void* __restrict__ mask) {
    __shared__ float Qs[64][68];   // [d][i]
    __shared__ float Ks[64][68];   // [d][j]
    __shared__ float m_run[64];
    __shared__ float l_run[64];

    const int iTile = blockIdx.x, h = blockIdx.y, b = blockIdx.z;
    const int tx = threadIdx.x, ty = threadIdx.y;
    const int tid = ty * 16 + tx;
    const int bh = b * NH + h;

    const float* __restrict__ Q = g_Q + (size_t)bh * NA * D_DIM;
    const float* __restrict__ K = g_K + (size_t)bh * NA * D_DIM;
    const float invTP = 0.08838834764831843f; // 1/sqrt(2*64)

    // stage Q tile transposed
    for (int t = tid; t < 1024; t += 256) {
        int r = t >> 4, dq = (t & 15) * 4;
        float4 v = *(const float4*)&Q[(size_t)(iTile * 64 + r) * D_DIM + dq];
        Qs[dq + 0][r] = v.x; Qs[dq + 1][r] = v.y; Qs[dq + 2][r] = v.z; Qs[dq + 3][r] = v.w;
    }
    if (tid < 64) { m_run[tid] = -3.0e38f; l_run[tid] = 0.0f; }

    const int mtype = g_maskType;

    for (int jt = 0; jt < NA / 64; jt++) {
        __syncthreads();
        // stage K tile transposed
        for (int t = tid; t < 1024; t += 256) {
            int r = t >> 4, dq = (t & 15) * 4;
            float4 v = *(const float4*)&K[(size_t)(jt * 64 + r) * D_DIM + dq];
            Ks[dq + 0][r] = v.x; Ks[dq + 1][r] = v.y; Ks[dq + 2][r] = v.z; Ks[dq + 3][r] = v.w;
        }
        __syncthreads();

        float acc[4][4];
#pragma unroll
        for (int i = 0; i < 4; i++)
#pragma unroll
            for (int j = 0; j < 4; j++) acc[i][j] = 0.0f;

#pragma unroll 16
        for (int kk = 0; kk < 64; kk++) {
            float a[4], bb[4];
            *(float4*)a  = *(const float4*)&Qs[kk][ty * 4];
            *(float4*)bb = *(const float4*)&Ks[kk][tx * 4];
#pragma unroll
            for (int i = 0; i < 4; i++)
#pragma unroll
                for (int j = 0; j < 4; j++) acc[i][j] += a[i] * bb[j];
        }

        const int jG = jt * 64 + tx * 4;
#pragma unroll
        for (int r = 0; r < 4; r++) {
            const int row = ty * 4 + r;                // local row
            const int iG = iTile * 64 + row;           // global i
            const size_t aoff = ((size_t)(b * NA + iG)) * NA + jG;

            float4 av = *(const float4*)&adj[aoff];
            float s[4];
            s[0] = acc[r][0] * invTP + av.x;
            s[1] = acc[r][1] * invTP + av.y;
            s[2] = acc[r][2] * invTP + av.z;
            s[3] = acc[r][3] * invTP + av.w;

            if (mtype == 0) {
                unsigned w = *(const unsigned*)((const uint8_t*)mask + aoff);
#pragma unroll
                for (int c = 0; c < 4; c++)
                    if ((w >> (8 * c)) & 0xFFu) s[c] = -1.0e30f;
            } else if (mtype == 1) {
                int4 mv = *(const int4*)&((const int*)mask)[aoff];
                if (mv.x) s[0] = -1.0e30f;
                if (mv.y) s[1] = -1.0e30f;
                if (mv.z) s[2] = -1.0e30f;
                if (mv.w) s[3] = -1.0e30f;
            } else {
                float4 mv = *(const float4*)&((const float*)mask)[aoff];
                if (mv.x != 0.0f) s[0] = -1.0e30f;
                if (mv.y != 0.0f) s[1] = -1.0e30f;
                if (mv.z != 0.0f) s[2] = -1.0e30f;
                if (mv.w != 0.0f) s[3] = -1.0e30f;
            }

            // write raw masked scores
            float4 sv; sv.x = s[0]; sv.y = s[1]; sv.z = s[2]; sv.w = s[3];
            *(float4*)&g_S[((size_t)bh * NA + iG) * NA + jG] = sv;

            // online max/sum across this row's 16 threads (one half-warp)
            float mx = fmaxf(fmaxf(s[0], s[1]), fmaxf(s[2], s[3]));
#pragma unroll
            for (int o = 8; o >= 1; o >>= 1)
                mx = fmaxf(mx, __shfl_xor_sync(0xFFFFFFFFu, mx, o));

            float mo = m_run[row];
            float mn = fmaxf(mo, mx);
            float pe = __expf(s[0] - mn) + __expf(s[1] - mn) +
                       __expf(s[2] - mn) + __expf(s[3] - mn);
#pragma unroll
            for (int o = 8; o >= 1; o >>= 1)
                pe += __shfl_xor_sync(0xFFFFFFFFu, pe, o);

            if (tx == 0) {
                l_run[row] = l_run[row] * __expf(mo - mn) + pe;
                m_run[row] = mn;
            }
        }
    }

    __syncthreads();
    if (tid < 64) {
        int iG = iTile * 64 + tid;
        g_m[bh * NA + iG] = m_run[tid];
        g_l[bh * NA + iG] = l_run[tid];
    }
}

// ---------------- kernel 3: out = softmax(S) @ V + x ----------------
// grid (NA/64, NH, NB), block (16,16). Block: 64 rows x all 64 d.
__global__ __launch_bounds__(256)
void av_kernel(const float* __restrict__ x, float* __restrict__ out) {
    __shared__ float Ps[64][68];   // [j][i], exp-normalized
    __shared__ float Vs[64][68];   // [j][d]
    __shared__ float ms[64];
    __shared__ float il[64];

    const int iTile = blockIdx.x, h = blockIdx.y, b = blockIdx.z;
    const int tx = threadIdx.x, ty = threadIdx.y;
    const int tid = ty * 16 + tx;
    const int bh = b * NH + h;

    const float* __restrict__ V = g_V + (size_t)bh * NA * D_DIM;
    const size_t Srow0 = ((size_t)bh * NA + (size_t)iTile * 64) * NA;

    if (tid < 64) {
        int iG = iTile * 64 + tid;
        ms[tid] = g_m[bh * NA + iG];
        il[tid] = 1.0f / g_l[bh * NA + iG];
    }

    float acc[4][4];
#pragma unroll
    for (int i = 0; i < 4; i++)
#pragma unroll
        for (int j = 0; j < 4; j++) acc[i][j] = 0.0f;

    for (int jt = 0; jt < NA / 64; jt++) {
        __syncthreads();
        // stage P transposed with exp applied
        for (int t = tid; t < 1024; t += 256) {
            int r = t >> 4, jq = (t & 15) * 4;
            float4 s4 = *(const float4*)&g_S[Srow0 + (size_t)r * NA + jt * 64 + jq];
            float mm = ms[r], ll = il[r];
            Ps[jq + 0][r] = __expf(s4.x - mm) * ll;
            Ps[jq + 1][r] = __expf(s4.y - mm) * ll;
            Ps[jq + 2][r] = __expf(s4.z - mm) * ll;
            Ps[jq + 3][r] = __expf(s4.w - mm) * ll;
        }
        // stage V direct
        for (int t = tid; t < 1024; t += 256) {
            int r = t >> 4, dq = (t & 15) * 4;
            float4 v = *(const float4*)&V[(size_t)(jt * 64 + r) * D_DIM + dq];
            *(float4*)&Vs[r][dq] = v;
        }
        __syncthreads();

#pragma unroll 16
        for (int kk = 0; kk < 64; kk++) {
            float a[4], bb[4];
            *(float4*)a  = *(const float4*)&Ps[kk][ty * 4];
            *(float4*)bb = *(const float4*)&Vs[kk][tx * 4];
#pragma unroll
            for (int i = 0; i < 4; i++)
#pragma unroll
                for (int j = 0; j < 4; j++) acc[i][j] += a[i] * bb[j];
        }
    }

    // epilogue: out[b][i][h*64+d] = acc + x
#pragma unroll
    for (int r = 0; r < 4; r++) {
        int iG = iTile * 64 + ty * 4 + r;
        size_t o = ((size_t)(b * NA + iG)) * C_DIM + h * D_DIM + tx * 4;
        float4 xv = *(const float4*)&x[o];
        float4 ov;
        ov.x = acc[r][0] + xv.x;
        ov.y = acc[r][1] + xv.y;
        ov.z = acc[r][2] + xv.z;
        ov.w = acc[r][3] + xv.w;
        *(float4*)&out[o] = ov;
    }
}

// ---------------- launch ----------------
extern "C" void kernel_launch(void* const* d_in, const int* in_sizes, int n_in,
                              void* d_out, int out_size) {
    const float* x    = (const float*)d_in[0];
    const void*  mask = d_in[1];
    const float* adj  = (const float*)d_in[2];
    const float* Wq   = (const float*)d_in[3];
    const float* Wk   = (const float*)d_in[4];
    const float* Wv   = (const float*)d_in[5];
    float* out = (float*)d_out;

    detect_mask_kernel<<<1, 256>>>((const unsigned int*)mask);

    dim3 blk(16, 16);
    dim3 g1(NB * NA / 128, C_DIM / 128, 3);
    qkv_gemm_kernel<<<g1, blk>>>(x, Wq, Wk, Wv);

    dim3 g2(NA / 64, NH, NB);
    scores_kernel<<<g2, blk>>>(adj, mask);

    dim3 g3(NA / 64, NH, NB);
    av_kernel<<<g3, blk>>>(x, out);
}

// round 2
// speedup vs baseline: 1.6006x; 1.6006x over previous
#include <cuda_runtime.h>
#include <cstdint>
#include <cstddef>

#define NB 16
#define NA 1024
#define C_DIM 512
#define NH 8
#define D_DIM 64

// ---------------- device scratch ----------------
__device__ float g_Q[(size_t)NB * NH * NA * D_DIM];   // [b][h][i][d]
__device__ float g_K[(size_t)NB * NH * NA * D_DIM];
__device__ float g_V[(size_t)NB * NH * NA * D_DIM];
__device__ int   g_maskType;                          // 0=u8, 1=i32, 2=f32

// ---------------- helpers ----------------
static __device__ __forceinline__ unsigned f2tf(float f) {
    unsigned u;
    asm("cvt.rna.tf32.f32 %0, %1;" : "=r"(u) : "f"(f));
    return u;
}

static __device__ __forceinline__ void mma_tf32(float* d, const unsigned* a,
                                                const unsigned* b, const float* c) {
    asm volatile(
        "mma.sync.aligned.m16n8k8.row.col.f32.tf32.tf32.f32 "
        "{%0,%1,%2,%3}, {%4,%5,%6,%7}, {%8,%9}, {%10,%11,%12,%13};"
        : "=f"(d[0]), "=f"(d[1]), "=f"(d[2]), "=f"(d[3])
        : "r"(a[0]), "r"(a[1]), "r"(a[2]), "r"(a[3]),
          "r"(b[0]), "r"(b[1]),
          "f"(c[0]), "f"(c[1]), "f"(c[2]), "f"(c[3]));
}

// ---------------- kernel 0: detect mask dtype ----------------
__global__ void detect_mask_kernel(const unsigned int* __restrict__ mw) {
    int gt1 = 0, f32 = 0;
    for (int t = threadIdx.x; t < 4096; t += 256) {
        unsigned v = mw[t];
        if (v == 0x3F800000u) f32 = 1;
        else if (v > 1u) gt1 = 1;
    }
    gt1 = __syncthreads_or(gt1);
    f32 = __syncthreads_or(f32);
    if (threadIdx.x == 0) g_maskType = f32 ? 2 : (gt1 ? 0 : 1);
}

// ---------------- kernel 1: QKV projection (tf32 tensor cores) ----------------
// Y = x(16384x512) @ W(512x512)^T -> [b][h][i][d]
// 256 thr = 8 warps, block tile 128m x 128n, BK=32. Warp tile 64m x 32n.
__global__ __launch_bounds__(256)
void qkv_gemm_tc(const float* __restrict__ x,
                 const float* __restrict__ Wq,
                 const float* __restrict__ Wk,
                 const float* __restrict__ Wv) {
    __shared__ unsigned As[128][36];   // [m][k], stride 36 -> conflict-free frags
    __shared__ unsigned Bs[128][36];   // [n][k]

    const int z = blockIdx.z;
    const float* __restrict__ W = (z == 0) ? Wq : (z == 1) ? Wk : Wv;
    float* __restrict__ outp = (z == 0) ? g_Q : (z == 1) ? g_K : g_V;

    const int mBase = blockIdx.x * 128;
    const int nBase = blockIdx.y * 128;
    const int tid = threadIdx.x;
    const int lane = tid & 31;
    const int warp = tid >> 5;
    const int q = lane & 3, r = lane >> 2;
    const int wm = warp & 1, wn = warp >> 1;   // warp grid 2m x 4n

    const int srow = tid >> 3;          // 0..31
    const int skq = (tid & 7) * 4;      // 0..28

    float4 ax[4], bx[4];
#pragma unroll
    for (int s = 0; s < 4; s++) {
        ax[s] = *(const float4*)&x[(size_t)(mBase + srow + 32 * s) * C_DIM + skq];
        bx[s] = *(const float4*)&W[(size_t)(nBase + srow + 32 * s) * C_DIM + skq];
    }

    float acc[4][4][4];
#pragma unroll
    for (int mf = 0; mf < 4; mf++)
#pragma unroll
        for (int nf = 0; nf < 4; nf++)
#pragma unroll
            for (int c = 0; c < 4; c++) acc[mf][nf][c] = 0.0f;

    for (int k0 = 0; k0 < C_DIM; k0 += 32) {
        __syncthreads();
#pragma unroll
        for (int s = 0; s < 4; s++) {
            int row = srow + 32 * s;
            As[row][skq + 0] = f2tf(ax[s].x); As[row][skq + 1] = f2tf(ax[s].y);
            As[row][skq + 2] = f2tf(ax[s].z); As[row][skq + 3] = f2tf(ax[s].w);
            Bs[row][skq + 0] = f2tf(bx[s].x); Bs[row][skq + 1] = f2tf(bx[s].y);
            Bs[row][skq + 2] = f2tf(bx[s].z); Bs[row][skq + 3] = f2tf(bx[s].w);
        }
        __syncthreads();

        if (k0 + 32 < C_DIM) {
#pragma unroll
            for (int s = 0; s < 4; s++) {
                ax[s] = *(const float4*)&x[(size_t)(mBase + srow + 32 * s) * C_DIM + k0 + 32 + skq];
                bx[s] = *(const float4*)&W[(size_t)(nBase + srow + 32 * s) * C_DIM + k0 + 32 + skq];
            }
        }

#pragma unroll
        for (int ks = 0; ks < 4; ks++) {
            unsigned af[4][4], bf[4][2];
#pragma unroll
            for (int mf = 0; mf < 4; mf++) {
                int rw = wm * 64 + mf * 16 + r;
                af[mf][0] = As[rw][ks * 8 + q];
                af[mf][1] = As[rw + 8][ks * 8 + q];
                af[mf][2] = As[rw][ks * 8 + q + 4];
                af[mf][3] = As[rw + 8][ks * 8 + q + 4];
            }
#pragma unroll
            for (int nf = 0; nf < 4; nf++) {
                int cn = wn * 32 + nf * 8 + r;
                bf[nf][0] = Bs[cn][ks * 8 + q];
                bf[nf][1] = Bs[cn][ks * 8 + q + 4];
            }
#pragma unroll
            for (int mf = 0; mf < 4; mf++)
#pragma unroll
                for (int nf = 0; nf < 4; nf++)
                    mma_tf32(acc[mf][nf], af[mf], bf[nf], acc[mf][nf]);
        }
    }

    // epilogue: frag rows m, cols n -> (h,d) of [b][h][i][d]
#pragma unroll
    for (int mf = 0; mf < 4; mf++) {
        int mG = mBase + wm * 64 + mf * 16 + r;
#pragma unroll
        for (int nf = 0; nf < 4; nf++) {
            int nG = nBase + wn * 32 + nf * 8 + 2 * q;
            int h = nG >> 6, d = nG & 63;
            {
                int bb = mG >> 10, ii = mG & 1023;
                float2 v = { acc[mf][nf][0], acc[mf][nf][1] };
                *(float2*)&outp[(((size_t)(bb * NH + h) * NA + ii) * D_DIM) + d] = v;
            }
            {
                int mG2 = mG + 8;
                int bb = mG2 >> 10, ii = mG2 & 1023;
                float2 v = { acc[mf][nf][2], acc[mf][nf][3] };
                *(float2*)&outp[(((size_t)(bb * NH + h) * NA + ii) * D_DIM) + d] = v;
            }
        }
    }
}

// ---------------- kernel 2: fused flash attention (tf32 tensor cores) ----------------
// grid (NA/64, NH, NB), 128 threads = 4 warps. Each warp owns 16 query rows.
// S = QK^T/TP + adj (masked); online softmax; O += P@V with rescaling. No S in HBM.
__global__ __launch_bounds__(128)
void flash_tc(const float* __restrict__ adj, const void* __restrict__ mask,
              const float* __restrict__ x, float* __restrict__ out) {
    extern __shared__ unsigned sm[];
    unsigned (*Ps)[68] = (unsigned(*)[68])sm;                 // Q staging, then P tiles
    unsigned (*Ks)[68] = (unsigned(*)[68])(sm + 64 * 68);
    unsigned (*Vs)[72] = (unsigned(*)[72])(sm + 2 * 64 * 68);

    const int iT = blockIdx.x, h = blockIdx.y, b = blockIdx.z;
    const int tid = threadIdx.x;
    const int lane = tid & 31;
    const int w = tid >> 5;
    const int q = lane & 3, r = lane >> 2;
    const int w16 = w * 16;

    const float* __restrict__ Qp = g_Q + (size_t)(b * NH + h) * NA * D_DIM;
    const float* __restrict__ Kp = g_K + (size_t)(b * NH + h) * NA * D_DIM;
    const float* __restrict__ Vp = g_V + (size_t)(b * NH + h) * NA * D_DIM;

    // stage Q (64 rows x 64 d) into Ps, tf32
#pragma unroll
    for (int s = 0; s < 8; s++) {
        int slot = s * 128 + tid;
        int row = slot >> 4, cq = (slot & 15) * 4;
        float4 v = *(const float4*)&Qp[(size_t)(iT * 64 + row) * D_DIM + cq];
        Ps[row][cq + 0] = f2tf(v.x); Ps[row][cq + 1] = f2tf(v.y);
        Ps[row][cq + 2] = f2tf(v.z); Ps[row][cq + 3] = f2tf(v.w);
    }
    __syncthreads();

    // Q fragments in registers for entire kernel
    unsigned qf[8][4];
#pragma unroll
    for (int kf = 0; kf < 8; kf++) {
        qf[kf][0] = Ps[w16 + r][kf * 8 + q];
        qf[kf][1] = Ps[w16 + r + 8][kf * 8 + q];
        qf[kf][2] = Ps[w16 + r][kf * 8 + q + 4];
        qf[kf][3] = Ps[w16 + r + 8][kf * 8 + q + 4];
    }

    float accO[8][4];
#pragma unroll
    for (int nf = 0; nf < 8; nf++)
#pragma unroll
        for (int c = 0; c < 4; c++) accO[nf][c] = 0.0f;

    float m0 = -3.0e38f, m1 = -3.0e38f, l0 = 0.0f, l1 = 0.0f;
    const int mt = g_maskType;
    const float invTP = 0.08838834764831843f;  // 1/sqrt(2*64)
    const int iG0 = iT * 64 + w16 + r;         // rows iG0 and iG0+8

    for (int jt = 0; jt < NA / 64; jt++) {
        __syncthreads();   // everyone done with previous Ks/Vs
#pragma unroll
        for (int s = 0; s < 8; s++) {
            int slot = s * 128 + tid;
            int row = slot >> 4, cq = (slot & 15) * 4;
            float4 kv = *(const float4*)&Kp[(size_t)(jt * 64 + row) * D_DIM + cq];
            float4 vv = *(const float4*)&Vp[(size_t)(jt * 64 + row) * D_DIM + cq];
            Ks[row][cq + 0] = f2tf(kv.x); Ks[row][cq + 1] = f2tf(kv.y);
            Ks[row][cq + 2] = f2tf(kv.z); Ks[row][cq + 3] = f2tf(kv.w);
            Vs[row][cq + 0] = f2tf(vv.x); Vs[row][cq + 1] = f2tf(vv.y);
            Vs[row][cq + 2] = f2tf(vv.z); Vs[row][cq + 3] = f2tf(vv.w);
        }
        __syncthreads();

        // --- S = Q @ K^T (per-warp 16 x 64 tile) ---
        float sa[8][4];
#pragma unroll
        for (int nf = 0; nf < 8; nf++)
#pragma unroll
            for (int c = 0; c < 4; c++) sa[nf][c] = 0.0f;

#pragma unroll
        for (int nf = 0; nf < 8; nf++) {
            const unsigned* krow = &Ks[nf * 8 + r][0];
#pragma unroll
            for (int kf = 0; kf < 8; kf++) {
                unsigned bf[2] = { krow[kf * 8 + q], krow[kf * 8 + q + 4] };
                mma_tf32(sa[nf], qf[kf], bf, sa[nf]);
            }
        }

        // --- scale + adjacency + mask (fp32) ---
#pragma unroll
        for (int nf = 0; nf < 8; nf++) {
            int jG = jt * 64 + nf * 8 + 2 * q;
            size_t o0 = ((size_t)b * NA + iG0) * NA + jG;
            size_t o1 = o0 + (size_t)8 * NA;
            float2 a0 = *(const float2*)&adj[o0];
            float2 a1 = *(const float2*)&adj[o1];
            sa[nf][0] = fmaf(sa[nf][0], invTP, a0.x);
            sa[nf][1] = fmaf(sa[nf][1], invTP, a0.y);
            sa[nf][2] = fmaf(sa[nf][2], invTP, a1.x);
            sa[nf][3] = fmaf(sa[nf][3], invTP, a1.y);
            if (mt == 0) {
                uint16_t w0 = *(const uint16_t*)((const uint8_t*)mask + o0);
                uint16_t w1 = *(const uint16_t*)((const uint8_t*)mask + o1);
                if (w0 & 0x00FF) sa[nf][0] = -1.0e30f;
                if (w0 & 0xFF00) sa[nf][1] = -1.0e30f;
                if (w1 & 0x00FF) sa[nf][2] = -1.0e30f;
                if (w1 & 0xFF00) sa[nf][3] = -1.0e30f;
            } else if (mt == 1) {
                int2 z0 = *(const int2*)((const int*)mask + o0);
                int2 z1 = *(const int2*)((const int*)mask + o1);
                if (z0.x) sa[nf][0] = -1.0e30f;
                if (z0.y) sa[nf][1] = -1.0e30f;
                if (z1.x) sa[nf][2] = -1.0e30f;
                if (z1.y) sa[nf][3] = -1.0e30f;
            } else {
                float2 z0 = *(const float2*)((const float*)mask + o0);
                float2 z1 = *(const float2*)((const float*)mask + o1);
                if (z0.x != 0.0f) sa[nf][0] = -1.0e30f;
                if (z0.y != 0.0f) sa[nf][1] = -1.0e30f;
                if (z1.x != 0.0f) sa[nf][2] = -1.0e30f;
                if (z1.y != 0.0f) sa[nf][3] = -1.0e30f;
            }
        }

        // --- online softmax update (rows iG0, iG0+8 per thread) ---
        float mx0 = -3.0e38f, mx1 = -3.0e38f;
#pragma unroll
        for (int nf = 0; nf < 8; nf++) {
            mx0 = fmaxf(mx0, fmaxf(sa[nf][0], sa[nf][1]));
            mx1 = fmaxf(mx1, fmaxf(sa[nf][2], sa[nf][3]));
        }
        mx0 = fmaxf(mx0, __shfl_xor_sync(0xFFFFFFFFu, mx0, 1));
        mx0 = fmaxf(mx0, __shfl_xor_sync(0xFFFFFFFFu, mx0, 2));
        mx1 = fmaxf(mx1, __shfl_xor_sync(0xFFFFFFFFu, mx1, 1));
        mx1 = fmaxf(mx1, __shfl_xor_sync(0xFFFFFFFFu, mx1, 2));

        float mn0 = fmaxf(m0, mx0), mn1 = fmaxf(m1, mx1);
        float sc0 = __expf(m0 - mn0), sc1 = __expf(m1 - mn1);
        m0 = mn0; m1 = mn1;

        float p0 = 0.0f, p1 = 0.0f;
#pragma unroll
        for (int nf = 0; nf < 8; nf++) {
            sa[nf][0] = __expf(sa[nf][0] - mn0); p0 += sa[nf][0];
            sa[nf][1] = __expf(sa[nf][1] - mn0); p0 += sa[nf][1];
            sa[nf][2] = __expf(sa[nf][2] - mn1); p1 += sa[nf][2];
            sa[nf][3] = __expf(sa[nf][3] - mn1); p1 += sa[nf][3];
        }
        p0 += __shfl_xor_sync(0xFFFFFFFFu, p0, 1);
        p0 += __shfl_xor_sync(0xFFFFFFFFu, p0, 2);
        p1 += __shfl_xor_sync(0xFFFFFFFFu, p1, 1);
        p1 += __shfl_xor_sync(0xFFFFFFFFu, p1, 2);
        l0 = l0 * sc0 + p0;
        l1 = l1 * sc1 + p1;

#pragma unroll
        for (int nf = 0; nf < 8; nf++) {
            accO[nf][0] *= sc0; accO[nf][1] *= sc0;
            accO[nf][2] *= sc1; accO[nf][3] *= sc1;
        }

        // --- write P to warp-private smem rows (tf32), then PV mma ---
#pragma unroll
        for (int nf = 0; nf < 8; nf++) {
            Ps[w16 + r][nf * 8 + 2 * q] = f2tf(sa[nf][0]);
            Ps[w16 + r][nf * 8 + 2 * q + 1] = f2tf(sa[nf][1]);
            Ps[w16 + r + 8][nf * 8 + 2 * q] = f2tf(sa[nf][2]);
            Ps[w16 + r + 8][nf * 8 + 2 * q + 1] = f2tf(sa[nf][3]);
        }
        __syncwarp();

#pragma unroll
        for (int kf = 0; kf < 8; kf++) {
            unsigned pa[4];
            pa[0] = Ps[w16 + r][kf * 8 + q];
            pa[1] = Ps[w16 + r + 8][kf * 8 + q];
            pa[2] = Ps[w16 + r][kf * 8 + q + 4];
            pa[3] = Ps[w16 + r + 8][kf * 8 + q + 4];
#pragma unroll
            for (int nf = 0; nf < 8; nf++) {
                unsigned bf[2] = { Vs[kf * 8 + q][nf * 8 + r],
                                   Vs[kf * 8 + q + 4][nf * 8 + r] };
                mma_tf32(accO[nf], pa, bf, accO[nf]);
            }
        }
        __syncwarp();   // protect Ps rows before next iteration's writes
    }

    // --- epilogue: out = accO / l + x ---
    float li0 = 1.0f / l0, li1 = 1.0f / l1;
#pragma unroll
    for (int nf = 0; nf < 8; nf++) {
        int cG = h * 64 + nf * 8 + 2 * q;
        size_t o0 = ((size_t)(b * NA + iG0)) * C_DIM + cG;
        size_t o1 = ((size_t)(b * NA + iG0 + 8)) * C_DIM + cG;
        float2 x0 = *(const float2*)&x[o0];
        float2 x1 = *(const float2*)&x[o1];
        float2 r0 = { accO[nf][0] * li0 + x0.x, accO[nf][1] * li0 + x0.y };
        float2 r1 = { accO[nf][2] * li1 + x1.x, accO[nf][3] * li1 + x1.y };
        *(float2*)&out[o0] = r0;
        *(float2*)&out[o1] = r1;
    }
}

// ---------------- launch ----------------
#define SMEM_FLASH ((2 * 64 * 68 + 64 * 72) * 4)

extern "C" void kernel_launch(void* const* d_in, const int* in_sizes, int n_in,
                              void* d_out, int out_size) {
    const float* x    = (const float*)d_in[0];
    const void*  mask = d_in[1];
    const float* adj  = (const float*)d_in[2];
    const float* Wq   = (const float*)d_in[3];
    const float* Wk   = (const float*)d_in[4];
    const float* Wv   = (const float*)d_in[5];
    float* out = (float*)d_out;

    detect_mask_kernel<<<1, 256>>>((const unsigned int*)mask);

    dim3 g1(NB * NA / 128, C_DIM / 128, 3);
    qkv_gemm_tc<<<g1, 256>>>(x, Wq, Wk, Wv);

    cudaFuncSetAttribute(flash_tc, cudaFuncAttributeMaxDynamicSharedMemorySize, SMEM_FLASH);
    dim3 g2(NA / 64, NH, NB);
    flash_tc<<<g2, 128, SMEM_FLASH>>>(adj, mask, x, out);
}

// round 3
// speedup vs baseline: 2.3521x; 1.4696x over previous
#include <cuda_runtime.h>
#include <cstdint>
#include <cstddef>

#define NB 16
#define NA 1024
#define C_DIM 512
#define NH 8
#define D_DIM 64

// ---------------- device scratch ----------------
__device__ float g_Q[(size_t)NB * NH * NA * D_DIM];   // [b][h][i][d]  (pre-scaled by 1/TP)
__device__ float g_K[(size_t)NB * NH * NA * D_DIM];
__device__ float g_V[(size_t)NB * NH * NA * D_DIM];
__device__ int   g_maskType;                          // 0=u8, 1=i32, 2=f32

// ---------------- helpers ----------------
static __device__ __forceinline__ void mma_tf32(float* d, const unsigned* a,
                                                const unsigned* b, const float* c) {
    asm volatile(
        "mma.sync.aligned.m16n8k8.row.col.f32.tf32.tf32.f32 "
        "{%0,%1,%2,%3}, {%4,%5,%6,%7}, {%8,%9}, {%10,%11,%12,%13};"
        : "=f"(d[0]), "=f"(d[1]), "=f"(d[2]), "=f"(d[3])
        : "r"(a[0]), "r"(a[1]), "r"(a[2]), "r"(a[3]),
          "r"(b[0]), "r"(b[1]),
          "f"(c[0]), "f"(c[1]), "f"(c[2]), "f"(c[3]));
}

static __device__ __forceinline__ void cp16(void* smem, const void* g) {
    unsigned saddr = (unsigned)__cvta_generic_to_shared(smem);
    asm volatile("cp.async.cg.shared.global [%0], [%1], 16;\n" :: "r"(saddr), "l"(g));
}
static __device__ __forceinline__ void cp_commit() {
    asm volatile("cp.async.commit_group;\n" ::: "memory");
}
template <int N>
static __device__ __forceinline__ void cp_wait() {
    asm volatile("cp.async.wait_group %0;\n" :: "n"(N) : "memory");
}

// ---------------- kernel 0: detect mask dtype ----------------
__global__ void detect_mask_kernel(const unsigned int* __restrict__ mw) {
    int gt1 = 0, f32 = 0;
    for (int t = threadIdx.x; t < 4096; t += 256) {
        unsigned v = mw[t];
        if (v == 0x3F800000u) f32 = 1;
        else if (v > 1u) gt1 = 1;
    }
    gt1 = __syncthreads_or(gt1);
    f32 = __syncthreads_or(f32);
    if (threadIdx.x == 0) g_maskType = f32 ? 2 : (gt1 ? 0 : 1);
}

// ---------------- kernel 1: QKV projection (tf32 MMA, cp.async double-buffered) ----------------
// Y = x(16384x512) @ W(512x512)^T -> [b][h][i][d]; Q pre-scaled by 1/TP.
__global__ __launch_bounds__(256, 2)
void qkv_gemm_tc(const float* __restrict__ x,
                 const float* __restrict__ Wq,
                 const float* __restrict__ Wk,
                 const float* __restrict__ Wv) {
    __shared__ unsigned As[2][128 * 36];   // [m][k], raw fp32 bits as tf32
    __shared__ unsigned Bs[2][128 * 36];   // [n][k]

    const int z = blockIdx.z;
    const float* __restrict__ W = (z == 0) ? Wq : (z == 1) ? Wk : Wv;
    float* __restrict__ outp = (z == 0) ? g_Q : (z == 1) ? g_K : g_V;

    const int mBase = blockIdx.x * 128;
    const int nBase = blockIdx.y * 128;
    const int tid = threadIdx.x;
    const int lane = tid & 31;
    const int warp = tid >> 5;
    const int q = lane & 3, r = lane >> 2;
    const int wm = warp & 1, wn = warp >> 1;   // warp grid 2m x 4n

    const int srow = tid >> 3;          // 0..31
    const int skq = (tid & 7) * 4;      // 0..28

    auto loadAB = [&](int buf, int k0) {
#pragma unroll
        for (int s = 0; s < 4; s++) {
            int row = srow + 32 * s;
            cp16(&As[buf][row * 36 + skq], &x[(size_t)(mBase + row) * C_DIM + k0 + skq]);
            cp16(&Bs[buf][row * 36 + skq], &W[(size_t)(nBase + row) * C_DIM + k0 + skq]);
        }
    };

    float acc[4][4][4];
#pragma unroll
    for (int mf = 0; mf < 4; mf++)
#pragma unroll
        for (int nf = 0; nf < 4; nf++)
#pragma unroll
            for (int c = 0; c < 4; c++) acc[mf][nf][c] = 0.0f;

    loadAB(0, 0);
    cp_commit();

    for (int step = 0; step < 16; step++) {
        const int cur = step & 1;
        __syncthreads();                       // prev compute done with buf cur^1
        if (step < 15) { loadAB(cur ^ 1, (step + 1) * 32); cp_commit(); }
        if (step < 15) cp_wait<1>(); else cp_wait<0>();
        __syncthreads();                       // buf cur visible to all

        const unsigned* __restrict__ A = As[cur];
        const unsigned* __restrict__ B = Bs[cur];
#pragma unroll
        for (int ks = 0; ks < 4; ks++) {
            unsigned af[4][4], bf[4][2];
#pragma unroll
            for (int mf = 0; mf < 4; mf++) {
                int rw = wm * 64 + mf * 16 + r;
                af[mf][0] = A[rw * 36 + ks * 8 + q];
                af[mf][1] = A[(rw + 8) * 36 + ks * 8 + q];
                af[mf][2] = A[rw * 36 + ks * 8 + q + 4];
                af[mf][3] = A[(rw + 8) * 36 + ks * 8 + q + 4];
            }
#pragma unroll
            for (int nf = 0; nf < 4; nf++) {
                int cn = wn * 32 + nf * 8 + r;
                bf[nf][0] = B[cn * 36 + ks * 8 + q];
                bf[nf][1] = B[cn * 36 + ks * 8 + q + 4];
            }
#pragma unroll
            for (int mf = 0; mf < 4; mf++)
#pragma unroll
                for (int nf = 0; nf < 4; nf++)
                    mma_tf32(acc[mf][nf], af[mf], bf[nf], acc[mf][nf]);
        }
    }

    const float sc = (z == 0) ? 0.08838834764831843f : 1.0f;  // 1/sqrt(2*64) folded into Q
#pragma unroll
    for (int mf = 0; mf < 4; mf++) {
        int mG = mBase + wm * 64 + mf * 16 + r;
#pragma unroll
        for (int nf = 0; nf < 4; nf++) {
            int nG = nBase + wn * 32 + nf * 8 + 2 * q;
            int h = nG >> 6, d = nG & 63;
            {
                int bb = mG >> 10, ii = mG & 1023;
                float2 v = { acc[mf][nf][0] * sc, acc[mf][nf][1] * sc };
                *(float2*)&outp[(((size_t)(bb * NH + h) * NA + ii) * D_DIM) + d] = v;
            }
            {
                int mG2 = mG + 8;
                int bb = mG2 >> 10, ii = mG2 & 1023;
                float2 v = { acc[mf][nf][2] * sc, acc[mf][nf][3] * sc };
                *(float2*)&outp[(((size_t)(bb * NH + h) * NA + ii) * D_DIM) + d] = v;
            }
        }
    }
}

// ---------------- kernel 2: fused flash attention ----------------
// grid (NH, NA/128, NB): h fastest -> 8 heads share adjacency strip in L2.
// 256 thr = 8 warps; Q tile 128 rows (warp w owns rows w*16..w*16+15).
// K/V 64-key tiles, cp.async double-buffered.
__global__ __launch_bounds__(256, 2)
void flash_tc(const float* __restrict__ adj, const void* __restrict__ mask,
              const float* __restrict__ x, float* __restrict__ out) {
    extern __shared__ unsigned sm[];
    unsigned* Pb = sm;                       // 128*68: Q staging, then per-warp P tiles
    unsigned* Kb = sm + 128 * 68;            // 2 x 64*68
    unsigned* Vb = Kb + 2 * 64 * 68;         // 2 x 64*72

    const int h = blockIdx.x, iT = blockIdx.y, b = blockIdx.z;
    const int tid = threadIdx.x;
    const int lane = tid & 31;
    const int w = tid >> 5;
    const int q = lane & 3, r = lane >> 2;
    const int w16 = w * 16;

    const float* __restrict__ Qp = g_Q + (size_t)(b * NH + h) * NA * D_DIM;
    const float* __restrict__ Kp = g_K + (size_t)(b * NH + h) * NA * D_DIM;
    const float* __restrict__ Vp = g_V + (size_t)(b * NH + h) * NA * D_DIM;

    // stage Q (128 x 64) raw bits into P region
#pragma unroll
    for (int s = 0; s < 8; s++) {
        int slot = s * 256 + tid;
        int row = slot >> 4, cq = (slot & 15) * 4;
        float4 v = *(const float4*)&Qp[(size_t)(iT * 128 + row) * D_DIM + cq];
        *(float4*)&Pb[row * 68 + cq] = v;
    }

    auto loadKV = [&](int buf, int jt) {
        unsigned* Kd = Kb + buf * (64 * 68);
        unsigned* Vd = Vb + buf * (64 * 72);
#pragma unroll
        for (int s = 0; s < 4; s++) {
            int slot = s * 256 + tid;
            int row = slot >> 4, cq = (slot & 15) * 4;
            cp16(&Kd[row * 68 + cq], &Kp[(size_t)(jt * 64 + row) * D_DIM + cq]);
            cp16(&Vd[row * 72 + cq], &Vp[(size_t)(jt * 64 + row) * D_DIM + cq]);
        }
    };

    loadKV(0, 0);
    cp_commit();
    __syncthreads();   // Q staged

    // Q fragments live in registers for whole kernel (warp-private rows)
    unsigned qf[8][4];
#pragma unroll
    for (int kf = 0; kf < 8; kf++) {
        qf[kf][0] = Pb[(w16 + r) * 68 + kf * 8 + q];
        qf[kf][1] = Pb[(w16 + r + 8) * 68 + kf * 8 + q];
        qf[kf][2] = Pb[(w16 + r) * 68 + kf * 8 + q + 4];
        qf[kf][3] = Pb[(w16 + r + 8) * 68 + kf * 8 + q + 4];
    }

    float accO[8][4];
#pragma unroll
    for (int nf = 0; nf < 8; nf++)
#pragma unroll
        for (int c = 0; c < 4; c++) accO[nf][c] = 0.0f;

    float m0 = -3.0e38f, m1 = -3.0e38f, l0 = 0.0f, l1 = 0.0f;
    const int mt = g_maskType;
    const int iG0 = iT * 128 + w16 + r;    // rows iG0 and iG0+8

    for (int jt = 0; jt < NA / 64; jt++) {
        const int cur = jt & 1;
        __syncthreads();                   // prev compute done with buf cur^1
        if (jt < NA / 64 - 1) { loadKV(cur ^ 1, jt + 1); cp_commit(); }
        if (jt < NA / 64 - 1) cp_wait<1>(); else cp_wait<0>();
        __syncthreads();                   // buf cur visible

        const unsigned* __restrict__ Ks = Kb + cur * (64 * 68);
        const unsigned* __restrict__ Vs = Vb + cur * (64 * 72);

        // --- S = Q @ K^T ---
        float sa[8][4];
#pragma unroll
        for (int nf = 0; nf < 8; nf++)
#pragma unroll
            for (int c = 0; c < 4; c++) sa[nf][c] = 0.0f;

#pragma unroll
        for (int nf = 0; nf < 8; nf++) {
            const unsigned* krow = &Ks[(nf * 8 + r) * 68];
#pragma unroll
            for (int kf = 0; kf < 8; kf++) {
                unsigned bf[2] = { krow[kf * 8 + q], krow[kf * 8 + q + 4] };
                mma_tf32(sa[nf], qf[kf], bf, sa[nf]);
            }
        }

        // --- + adjacency, mask (fp32; Q pre-scaled by 1/TP) ---
#pragma unroll
        for (int nf = 0; nf < 8; nf++) {
            int jG = jt * 64 + nf * 8 + 2 * q;
            size_t o0 = ((size_t)b * NA + iG0) * NA + jG;
            size_t o1 = o0 + (size_t)8 * NA;
            float2 a0 = *(const float2*)&adj[o0];
            float2 a1 = *(const float2*)&adj[o1];
            sa[nf][0] += a0.x;
            sa[nf][1] += a0.y;
            sa[nf][2] += a1.x;
            sa[nf][3] += a1.y;
            if (mt == 0) {
                uint16_t w0 = *(const uint16_t*)((const uint8_t*)mask + o0);
                uint16_t w1 = *(const uint16_t*)((const uint8_t*)mask + o1);
                if (w0 & 0x00FF) sa[nf][0] = -1.0e30f;
                if (w0 & 0xFF00) sa[nf][1] = -1.0e30f;
                if (w1 & 0x00FF) sa[nf][2] = -1.0e30f;
                if (w1 & 0xFF00) sa[nf][3] = -1.0e30f;
            } else if (mt == 1) {
                int2 z0 = *(const int2*)((const int*)mask + o0);
                int2 z1 = *(const int2*)((const int*)mask + o1);
                if (z0.x) sa[nf][0] = -1.0e30f;
                if (z0.y) sa[nf][1] = -1.0e30f;
                if (z1.x) sa[nf][2] = -1.0e30f;
                if (z1.y) sa[nf][3] = -1.0e30f;
            } else {
                float2 z0 = *(const float2*)((const float*)mask + o0);
                float2 z1 = *(const float2*)((const float*)mask + o1);
                if (z0.x != 0.0f) sa[nf][0] = -1.0e30f;
                if (z0.y != 0.0f) sa[nf][1] = -1.0e30f;
                if (z1.x != 0.0f) sa[nf][2] = -1.0e30f;
                if (z1.y != 0.0f) sa[nf][3] = -1.0e30f;
            }
        }

        // --- online softmax (rows iG0, iG0+8) ---
        float mx0 = -3.0e38f, mx1 = -3.0e38f;
#pragma unroll
        for (int nf = 0; nf < 8; nf++) {
            mx0 = fmaxf(mx0, fmaxf(sa[nf][0], sa[nf][1]));
            mx1 = fmaxf(mx1, fmaxf(sa[nf][2], sa[nf][3]));
        }
        mx0 = fmaxf(mx0, __shfl_xor_sync(0xFFFFFFFFu, mx0, 1));
        mx0 = fmaxf(mx0, __shfl_xor_sync(0xFFFFFFFFu, mx0, 2));
        mx1 = fmaxf(mx1, __shfl_xor_sync(0xFFFFFFFFu, mx1, 1));
        mx1 = fmaxf(mx1, __shfl_xor_sync(0xFFFFFFFFu, mx1, 2));

        float mn0 = fmaxf(m0, mx0), mn1 = fmaxf(m1, mx1);
        float sc0 = __expf(m0 - mn0), sc1 = __expf(m1 - mn1);
        m0 = mn0; m1 = mn1;

        float p0 = 0.0f, p1 = 0.0f;
#pragma unroll
        for (int nf = 0; nf < 8; nf++) {
            sa[nf][0] = __expf(sa[nf][0] - mn0); p0 += sa[nf][0];
            sa[nf][1] = __expf(sa[nf][1] - mn0); p0 += sa[nf][1];
            sa[nf][2] = __expf(sa[nf][2] - mn1); p1 += sa[nf][2];
            sa[nf][3] = __expf(sa[nf][3] - mn1); p1 += sa[nf][3];
        }
        p0 += __shfl_xor_sync(0xFFFFFFFFu, p0, 1);
        p0 += __shfl_xor_sync(0xFFFFFFFFu, p0, 2);
        p1 += __shfl_xor_sync(0xFFFFFFFFu, p1, 1);
        p1 += __shfl_xor_sync(0xFFFFFFFFu, p1, 2);
        l0 = l0 * sc0 + p0;
        l1 = l1 * sc1 + p1;

#pragma unroll
        for (int nf = 0; nf < 8; nf++) {
            accO[nf][0] *= sc0; accO[nf][1] *= sc0;
            accO[nf][2] *= sc1; accO[nf][3] *= sc1;
        }

        // --- P to warp-private smem rows, then PV mma ---
#pragma unroll
        for (int nf = 0; nf < 8; nf++) {
            Pb[(w16 + r) * 68 + nf * 8 + 2 * q]     = __float_as_uint(sa[nf][0]);
            Pb[(w16 + r) * 68 + nf * 8 + 2 * q + 1] = __float_as_uint(sa[nf][1]);
            Pb[(w16 + r + 8) * 68 + nf * 8 + 2 * q]     = __float_as_uint(sa[nf][2]);
            Pb[(w16 + r + 8) * 68 + nf * 8 + 2 * q + 1] = __float_as_uint(sa[nf][3]);
        }
        __syncwarp();

#pragma unroll
        for (int kf = 0; kf < 8; kf++) {
            unsigned pa[4];
            pa[0] = Pb[(w16 + r) * 68 + kf * 8 + q];
            pa[1] = Pb[(w16 + r + 8) * 68 + kf * 8 + q];
            pa[2] = Pb[(w16 + r) * 68 + kf * 8 + q + 4];
            pa[3] = Pb[(w16 + r + 8) * 68 + kf * 8 + q + 4];
#pragma unroll
            for (int nf = 0; nf < 8; nf++) {
                unsigned bf[2] = { Vs[(kf * 8 + q) * 72 + nf * 8 + r],
                                   Vs[(kf * 8 + q + 4) * 72 + nf * 8 + r] };
                mma_tf32(accO[nf], pa, bf, accO[nf]);
            }
        }
        __syncwarp();
    }

    // --- epilogue: out = accO / l + x ---
    float li0 = 1.0f / l0, li1 = 1.0f / l1;
#pragma unroll
    for (int nf = 0; nf < 8; nf++) {
        int cG = h * 64 + nf * 8 + 2 * q;
        size_t o0 = ((size_t)(b * NA + iG0)) * C_DIM + cG;
        size_t o1 = ((size_t)(b * NA + iG0 + 8)) * C_DIM + cG;
        float2 x0 = *(const float2*)&x[o0];
        float2 x1 = *(const float2*)&x[o1];
        float2 r0 = { accO[nf][0] * li0 + x0.x, accO[nf][1] * li0 + x0.y };
        float2 r1 = { accO[nf][2] * li1 + x1.x, accO[nf][3] * li1 + x1.y };
        *(float2*)&out[o0] = r0;
        *(float2*)&out[o1] = r1;
    }
}

// ---------------- launch ----------------
#define SMEM_FLASH ((128 * 68 + 2 * 64 * 68 + 2 * 64 * 72) * 4)

extern "C" void kernel_launch(void* const* d_in, const int* in_sizes, int n_in,
                              void* d_out, int out_size) {
    const float* x    = (const float*)d_in[0];
    const void*  mask = d_in[1];
    const float* adj  = (const float*)d_in[2];
    const float* Wq   = (const float*)d_in[3];
    const float* Wk   = (const float*)d_in[4];
    const float* Wv   = (const float*)d_in[5];
    float* out = (float*)d_out;

    detect_mask_kernel<<<1, 256>>>((const unsigned int*)mask);

    dim3 g1(NB * NA / 128, C_DIM / 128, 3);
    qkv_gemm_tc<<<g1, 256>>>(x, Wq, Wk, Wv);

    cudaFuncSetAttribute(flash_tc, cudaFuncAttributeMaxDynamicSharedMemorySize, SMEM_FLASH);
    dim3 g2(NH, NA / 128, NB);
    flash_tc<<<g2, 256, SMEM_FLASH>>>(adj, mask, x, out);
}

// round 4
// speedup vs baseline: 2.6219x; 1.1147x over previous
#include <cuda_runtime.h>
#include <cstdint>
#include <cstddef>

#define NB 16
#define NA 1024
#define C_DIM 512
#define NH 8
#define D_DIM 64

// ---------------- device scratch ----------------
__device__ float g_Q[(size_t)NB * NH * NA * D_DIM];   // [b][h][i][d]  (pre-scaled by 1/TP)
__device__ float g_K[(size_t)NB * NH * NA * D_DIM];
__device__ float g_V[(size_t)NB * NH * NA * D_DIM];
__device__ int   g_maskType;                          // 0=u8, 1=i32, 2=f32

// ---------------- helpers ----------------
static __device__ __forceinline__ void mma_tf32(float* d, const unsigned* a,
                                                const unsigned* b, const float* c) {
    asm volatile(
        "mma.sync.aligned.m16n8k8.row.col.f32.tf32.tf32.f32 "
        "{%0,%1,%2,%3}, {%4,%5,%6,%7}, {%8,%9}, {%10,%11,%12,%13};"
        : "=f"(d[0]), "=f"(d[1]), "=f"(d[2]), "=f"(d[3])
        : "r"(a[0]), "r"(a[1]), "r"(a[2]), "r"(a[3]),
          "r"(b[0]), "r"(b[1]),
          "f"(c[0]), "f"(c[1]), "f"(c[2]), "f"(c[3]));
}

static __device__ __forceinline__ void cp16(void* smem, const void* g) {
    unsigned saddr = (unsigned)__cvta_generic_to_shared(smem);
    asm volatile("cp.async.cg.shared.global [%0], [%1], 16;\n" :: "r"(saddr), "l"(g));
}
static __device__ __forceinline__ void cp_commit() {
    asm volatile("cp.async.commit_group;\n" ::: "memory");
}
template <int N>
static __device__ __forceinline__ void cp_wait() {
    asm volatile("cp.async.wait_group %0;\n" :: "n"(N) : "memory");
}

// ---------------- kernel 1: QKV projection (tf32 MMA, cp.async, single-barrier pipeline)
// Block (0,0,z=0) additionally detects the mask dtype (replaces a whole launch).
__global__ __launch_bounds__(256, 2)
void qkv_gemm_tc(const float* __restrict__ x,
                 const float* __restrict__ Wq,
                 const float* __restrict__ Wk,
                 const float* __restrict__ Wv,
                 const unsigned* __restrict__ maskw) {
    __shared__ unsigned As[2][128 * 36];
    __shared__ unsigned Bs[2][128 * 36];

    const int z = blockIdx.z;

    // --- folded mask-dtype detection (one block only) ---
    if (z == 0 && blockIdx.x == 0 && blockIdx.y == 0) {
        int gt1 = 0, f32 = 0;
        for (int t = threadIdx.x; t < 4096; t += 256) {
            unsigned v = maskw[t];
            if (v == 0x3F800000u) f32 = 1;
            else if (v > 1u) gt1 = 1;
        }
        gt1 = __syncthreads_or(gt1);
        f32 = __syncthreads_or(f32);
        if (threadIdx.x == 0) g_maskType = f32 ? 2 : (gt1 ? 0 : 1);
    }

    const float* __restrict__ W = (z == 0) ? Wq : (z == 1) ? Wk : Wv;
    float* __restrict__ outp = (z == 0) ? g_Q : (z == 1) ? g_K : g_V;

    const int mBase = blockIdx.x * 128;
    const int nBase = blockIdx.y * 128;
    const int tid = threadIdx.x;
    const int lane = tid & 31;
    const int warp = tid >> 5;
    const int q = lane & 3, r = lane >> 2;
    const int wm = warp & 1, wn = warp >> 1;

    const int srow = tid >> 3;
    const int skq = (tid & 7) * 4;

    auto loadAB = [&](int buf, int k0) {
#pragma unroll
        for (int s = 0; s < 4; s++) {
            int row = srow + 32 * s;
            cp16(&As[buf][row * 36 + skq], &x[(size_t)(mBase + row) * C_DIM + k0 + skq]);
            cp16(&Bs[buf][row * 36 + skq], &W[(size_t)(nBase + row) * C_DIM + k0 + skq]);
        }
    };

    float acc[4][4][4];
#pragma unroll
    for (int mf = 0; mf < 4; mf++)
#pragma unroll
        for (int nf = 0; nf < 4; nf++)
#pragma unroll
            for (int c = 0; c < 4; c++) acc[mf][nf][c] = 0.0f;

    loadAB(0, 0);
    cp_commit();

    for (int step = 0; step < 16; step++) {
        const int cur = step & 1;
        cp_wait<0>();
        __syncthreads();          // buf cur visible; everyone done with buf cur^1
        if (step < 15) { loadAB(cur ^ 1, (step + 1) * 32); cp_commit(); }

        const unsigned* __restrict__ A = As[cur];
        const unsigned* __restrict__ B = Bs[cur];
#pragma unroll
        for (int ks = 0; ks < 4; ks++) {
            unsigned af[4][4], bf[4][2];
#pragma unroll
            for (int mf = 0; mf < 4; mf++) {
                int rw = wm * 64 + mf * 16 + r;
                af[mf][0] = A[rw * 36 + ks * 8 + q];
                af[mf][1] = A[(rw + 8) * 36 + ks * 8 + q];
                af[mf][2] = A[rw * 36 + ks * 8 + q + 4];
                af[mf][3] = A[(rw + 8) * 36 + ks * 8 + q + 4];
            }
#pragma unroll
            for (int nf = 0; nf < 4; nf++) {
                int cn = wn * 32 + nf * 8 + r;
                bf[nf][0] = B[cn * 36 + ks * 8 + q];
                bf[nf][1] = B[cn * 36 + ks * 8 + q + 4];
            }
#pragma unroll
            for (int mf = 0; mf < 4; mf++)
#pragma unroll
                for (int nf = 0; nf < 4; nf++)
                    mma_tf32(acc[mf][nf], af[mf], bf[nf], acc[mf][nf]);
        }
    }

    const float sc = (z == 0) ? 0.08838834764831843f : 1.0f;  // 1/sqrt(2*64) into Q
#pragma unroll
    for (int mf = 0; mf < 4; mf++) {
        int mG = mBase + wm * 64 + mf * 16 + r;
#pragma unroll
        for (int nf = 0; nf < 4; nf++) {
            int nG = nBase + wn * 32 + nf * 8 + 2 * q;
            int h = nG >> 6, d = nG & 63;
            {
                int bb = mG >> 10, ii = mG & 1023;
                float2 v = { acc[mf][nf][0] * sc, acc[mf][nf][1] * sc };
                *(float2*)&outp[(((size_t)(bb * NH + h) * NA + ii) * D_DIM) + d] = v;
            }
            {
                int mG2 = mG + 8;
                int bb = mG2 >> 10, ii = mG2 & 1023;
                float2 v = { acc[mf][nf][2] * sc, acc[mf][nf][3] * sc };
                *(float2*)&outp[(((size_t)(bb * NH + h) * NA + ii) * D_DIM) + d] = v;
            }
        }
    }
}

// ---------------- kernel 2: fused flash attention ----------------
// grid (NH, NA/128, NB). 256 thr = 8 warps; warp w owns query rows w*16..+15.
// Adjacency is loaded straight into the MMA C accumulators (S = Q*K + adj via C-init);
// mask prefetched into 4-bit codes before the cp.async wait.
__global__ __launch_bounds__(256, 2)
void flash_tc(const float* __restrict__ adj, const void* __restrict__ mask,
              const float* __restrict__ x, float* __restrict__ out) {
    extern __shared__ unsigned sm[];
    unsigned* Pb = sm;                       // 128*68: Q staging, then per-warp P tiles
    unsigned* Kb = sm + 128 * 68;            // 2 x 64*68
    unsigned* Vb = Kb + 2 * 64 * 68;         // 2 x 64*72

    const int h = blockIdx.x, iT = blockIdx.y, b = blockIdx.z;
    const int tid = threadIdx.x;
    const int lane = tid & 31;
    const int w = tid >> 5;
    const int q = lane & 3, r = lane >> 2;
    const int w16 = w * 16;

    const float* __restrict__ Qp = g_Q + (size_t)(b * NH + h) * NA * D_DIM;
    const float* __restrict__ Kp = g_K + (size_t)(b * NH + h) * NA * D_DIM;
    const float* __restrict__ Vp = g_V + (size_t)(b * NH + h) * NA * D_DIM;

    auto loadKV = [&](int buf, int jt) {
        unsigned* Kd = Kb + buf * (64 * 68);
        unsigned* Vd = Vb + buf * (64 * 72);
#pragma unroll
        for (int s = 0; s < 4; s++) {
            int slot = s * 256 + tid;
            int row = slot >> 4, cq = (slot & 15) * 4;
            cp16(&Kd[row * 68 + cq], &Kp[(size_t)(jt * 64 + row) * D_DIM + cq]);
            cp16(&Vd[row * 72 + cq], &Vp[(size_t)(jt * 64 + row) * D_DIM + cq]);
        }
    };

    loadKV(0, 0);
    cp_commit();

    // stage Q (128 x 64) raw bits into P region
#pragma unroll
    for (int s = 0; s < 8; s++) {
        int slot = s * 256 + tid;
        int row = slot >> 4, cq = (slot & 15) * 4;
        float4 v = *(const float4*)&Qp[(size_t)(iT * 128 + row) * D_DIM + cq];
        *(float4*)&Pb[row * 68 + cq] = v;
    }
    __syncthreads();   // Q staged (cross-warp rows)

    unsigned qf[8][4];
#pragma unroll
    for (int kf = 0; kf < 8; kf++) {
        qf[kf][0] = Pb[(w16 + r) * 68 + kf * 8 + q];
        qf[kf][1] = Pb[(w16 + r + 8) * 68 + kf * 8 + q];
        qf[kf][2] = Pb[(w16 + r) * 68 + kf * 8 + q + 4];
        qf[kf][3] = Pb[(w16 + r + 8) * 68 + kf * 8 + q + 4];
    }

    float accO[8][4];
#pragma unroll
    for (int nf = 0; nf < 8; nf++)
#pragma unroll
        for (int c = 0; c < 4; c++) accO[nf][c] = 0.0f;

    float m0 = -3.0e38f, m1 = -3.0e38f, l0 = 0.0f, l1 = 0.0f;
    const int mt = g_maskType;
    const int iG0 = iT * 128 + w16 + r;    // rows iG0 and iG0+8

    for (int jt = 0; jt < NA / 64; jt++) {
        const int cur = jt & 1;

        // ---- prefetch BEFORE the pipeline wait: adj -> sa (MMA C-init), mask -> codes ----
        float sa[8][4];
        unsigned pre[8];
#pragma unroll
        for (int nf = 0; nf < 8; nf++) {
            int jG = jt * 64 + nf * 8 + 2 * q;
            size_t o0 = ((size_t)b * NA + iG0) * NA + jG;
            size_t o1 = o0 + (size_t)8 * NA;
            float2 a0 = *(const float2*)&adj[o0];
            float2 a1 = *(const float2*)&adj[o1];
            sa[nf][0] = a0.x; sa[nf][1] = a0.y;
            sa[nf][2] = a1.x; sa[nf][3] = a1.y;
            unsigned p = 0;
            if (mt == 0) {
                uint16_t w0 = *(const uint16_t*)((const uint8_t*)mask + o0);
                uint16_t w1 = *(const uint16_t*)((const uint8_t*)mask + o1);
                p = (w0 & 0x00FF ? 1u : 0u) | (w0 & 0xFF00 ? 2u : 0u) |
                    (w1 & 0x00FF ? 4u : 0u) | (w1 & 0xFF00 ? 8u : 0u);
            } else if (mt == 1) {
                int2 z0 = *(const int2*)((const int*)mask + o0);
                int2 z1 = *(const int2*)((const int*)mask + o1);
                p = (z0.x ? 1u : 0u) | (z0.y ? 2u : 0u) | (z1.x ? 4u : 0u) | (z1.y ? 8u : 0u);
            } else {
                float2 z0 = *(const float2*)((const float*)mask + o0);
                float2 z1 = *(const float2*)((const float*)mask + o1);
                p = (z0.x != 0.0f ? 1u : 0u) | (z0.y != 0.0f ? 2u : 0u) |
                    (z1.x != 0.0f ? 4u : 0u) | (z1.y != 0.0f ? 8u : 0u);
            }
            pre[nf] = p;
        }

        cp_wait<0>();
        __syncthreads();               // buf cur visible; all warps done with cur^1
        if (jt + 1 < NA / 64) { loadKV(cur ^ 1, jt + 1); cp_commit(); }

        const unsigned* __restrict__ Ks = Kb + cur * (64 * 68);
        const unsigned* __restrict__ Vs = Vb + cur * (64 * 72);

        // --- S = Q @ K^T + adj (adj seeded as C) ---
#pragma unroll
        for (int nf = 0; nf < 8; nf++) {
            const unsigned* krow = &Ks[(nf * 8 + r) * 68];
#pragma unroll
            for (int kf = 0; kf < 8; kf++) {
                unsigned bf[2] = { krow[kf * 8 + q], krow[kf * 8 + q + 4] };
                mma_tf32(sa[nf], qf[kf], bf, sa[nf]);
            }
        }

        // --- apply mask codes ---
#pragma unroll
        for (int nf = 0; nf < 8; nf++) {
            unsigned p = pre[nf];
            if (p & 1u) sa[nf][0] = -1.0e30f;
            if (p & 2u) sa[nf][1] = -1.0e30f;
            if (p & 4u) sa[nf][2] = -1.0e30f;
            if (p & 8u) sa[nf][3] = -1.0e30f;
        }

        // --- online softmax (rows iG0, iG0+8) ---
        float mx0 = -3.0e38f, mx1 = -3.0e38f;
#pragma unroll
        for (int nf = 0; nf < 8; nf++) {
            mx0 = fmaxf(mx0, fmaxf(sa[nf][0], sa[nf][1]));
            mx1 = fmaxf(mx1, fmaxf(sa[nf][2], sa[nf][3]));
        }
        mx0 = fmaxf(mx0, __shfl_xor_sync(0xFFFFFFFFu, mx0, 1));
        mx0 = fmaxf(mx0, __shfl_xor_sync(0xFFFFFFFFu, mx0, 2));
        mx1 = fmaxf(mx1, __shfl_xor_sync(0xFFFFFFFFu, mx1, 1));
        mx1 = fmaxf(mx1, __shfl_xor_sync(0xFFFFFFFFu, mx1, 2));

        float mn0 = fmaxf(m0, mx0), mn1 = fmaxf(m1, mx1);
        float sc0 = __expf(m0 - mn0), sc1 = __expf(m1 - mn1);
        m0 = mn0; m1 = mn1;

        float p0 = 0.0f, p1 = 0.0f;
#pragma unroll
        for (int nf = 0; nf < 8; nf++) {
            sa[nf][0] = __expf(sa[nf][0] - mn0); p0 += sa[nf][0];
            sa[nf][1] = __expf(sa[nf][1] - mn0); p0 += sa[nf][1];
            sa[nf][2] = __expf(sa[nf][2] - mn1); p1 += sa[nf][2];
            sa[nf][3] = __expf(sa[nf][3] - mn1); p1 += sa[nf][3];
        }
        p0 += __shfl_xor_sync(0xFFFFFFFFu, p0, 1);
        p0 += __shfl_xor_sync(0xFFFFFFFFu, p0, 2);
        p1 += __shfl_xor_sync(0xFFFFFFFFu, p1, 1);
        p1 += __shfl_xor_sync(0xFFFFFFFFu, p1, 2);
        l0 = l0 * sc0 + p0;
        l1 = l1 * sc1 + p1;

#pragma unroll
        for (int nf = 0; nf < 8; nf++) {
            accO[nf][0] *= sc0; accO[nf][1] *= sc0;
            accO[nf][2] *= sc1; accO[nf][3] *= sc1;
        }

        // --- P to warp-private smem rows, then PV mma ---
#pragma unroll
        for (int nf = 0; nf < 8; nf++) {
            Pb[(w16 + r) * 68 + nf * 8 + 2 * q]     = __float_as_uint(sa[nf][0]);
            Pb[(w16 + r) * 68 + nf * 8 + 2 * q + 1] = __float_as_uint(sa[nf][1]);
            Pb[(w16 + r + 8) * 68 + nf * 8 + 2 * q]     = __float_as_uint(sa[nf][2]);
            Pb[(w16 + r + 8) * 68 + nf * 8 + 2 * q + 1] = __float_as_uint(sa[nf][3]);
        }
        __syncwarp();

#pragma unroll
        for (int kf = 0; kf < 8; kf++) {
            unsigned pa[4];
            pa[0] = Pb[(w16 + r) * 68 + kf * 8 + q];
            pa[1] = Pb[(w16 + r + 8) * 68 + kf * 8 + q];
            pa[2] = Pb[(w16 + r) * 68 + kf * 8 + q + 4];
            pa[3] = Pb[(w16 + r + 8) * 68 + kf * 8 + q + 4];
#pragma unroll
            for (int nf = 0; nf < 8; nf++) {
                unsigned bf[2] = { Vs[(kf * 8 + q) * 72 + nf * 8 + r],
                                   Vs[(kf * 8 + q + 4) * 72 + nf * 8 + r] };
                mma_tf32(accO[nf], pa, bf, accO[nf]);
            }
        }
        __syncwarp();
    }

    // --- epilogue: out = accO / l + x ---
    float li0 = 1.0f / l0, li1 = 1.0f / l1;
#pragma unroll
    for (int nf = 0; nf < 8; nf++) {
        int cG = h * 64 + nf * 8 + 2 * q;
        size_t o0 = ((size_t)(b * NA + iG0)) * C_DIM + cG;
        size_t o1 = ((size_t)(b * NA + iG0 + 8)) * C_DIM + cG;
        float2 x0 = *(const float2*)&x[o0];
        float2 x1 = *(const float2*)&x[o1];
        float2 r0 = { accO[nf][0] * li0 + x0.x, accO[nf][1] * li0 + x0.y };
        float2 r1 = { accO[nf][2] * li1 + x1.x, accO[nf][3] * li1 + x1.y };
        *(float2*)&out[o0] = r0;
        *(float2*)&out[o1] = r1;
    }
}

// ---------------- launch ----------------
#define SMEM_FLASH ((128 * 68 + 2 * 64 * 68 + 2 * 64 * 72) * 4)

extern "C" void kernel_launch(void* const* d_in, const int* in_sizes, int n_in,
                              void* d_out, int out_size) {
    const float* x    = (const float*)d_in[0];
    const void*  mask = d_in[1];
    const float* adj  = (const float*)d_in[2];
    const float* Wq   = (const float*)d_in[3];
    const float* Wk   = (const float*)d_in[4];
    const float* Wv   = (const float*)d_in[5];
    float* out = (float*)d_out;

    dim3 g1(NB * NA / 128, C_DIM / 128, 3);
    qkv_gemm_tc<<<g1, 256>>>(x, Wq, Wk, Wv, (const unsigned*)mask);

    cudaFuncSetAttribute(flash_tc, cudaFuncAttributeMaxDynamicSharedMemorySize, SMEM_FLASH);
    dim3 g2(NH, NA / 128, NB);
    flash_tc<<<g2, 256, SMEM_FLASH>>>(adj, mask, x, out);
}

// round 5
// speedup vs baseline: 3.1627x; 1.2063x over previous
#include <cuda_runtime.h>
#include <cuda_fp16.h>
#include <cstdint>
#include <cstddef>

#define NB 16
#define NA 1024
#define C_DIM 512
#define NH 8
#define D_DIM 64

// ---------------- device scratch ----------------
__device__ float g_Q[(size_t)NB * NH * NA * D_DIM];   // [b][h][i][d]  (pre-scaled by 1/TP)
__device__ float g_K[(size_t)NB * NH * NA * D_DIM];
__device__ float g_V[(size_t)NB * NH * NA * D_DIM];
__device__ int   g_maskType;                          // 0=u8, 1=i32, 2=f32

// ---------------- helpers ----------------
static __device__ __forceinline__ void mma_tf32(float* d, const unsigned* a,
                                                const unsigned* b, const float* c) {
    asm volatile(
        "mma.sync.aligned.m16n8k8.row.col.f32.tf32.tf32.f32 "
        "{%0,%1,%2,%3}, {%4,%5,%6,%7}, {%8,%9}, {%10,%11,%12,%13};"
        : "=f"(d[0]), "=f"(d[1]), "=f"(d[2]), "=f"(d[3])
        : "r"(a[0]), "r"(a[1]), "r"(a[2]), "r"(a[3]),
          "r"(b[0]), "r"(b[1]),
          "f"(c[0]), "f"(c[1]), "f"(c[2]), "f"(c[3]));
}

static __device__ __forceinline__ void mma_f16(float* d, const unsigned* a,
                                               const unsigned* b) {
    asm volatile(
        "mma.sync.aligned.m16n8k16.row.col.f32.f16.f16.f32 "
        "{%0,%1,%2,%3}, {%4,%5,%6,%7}, {%8,%9}, {%0,%1,%2,%3};"
        : "+f"(d[0]), "+f"(d[1]), "+f"(d[2]), "+f"(d[3])
        : "r"(a[0]), "r"(a[1]), "r"(a[2]), "r"(a[3]),
          "r"(b[0]), "r"(b[1]));
}

static __device__ __forceinline__ unsigned packh2(float lo, float hi) {
    __half2 h = __floats2half2_rn(lo, hi);
    return *(unsigned*)&h;
}

static __device__ __forceinline__ void cp16(void* smem, const void* g) {
    unsigned saddr = (unsigned)__cvta_generic_to_shared(smem);
    asm volatile("cp.async.cg.shared.global [%0], [%1], 16;\n" :: "r"(saddr), "l"(g));
}
static __device__ __forceinline__ void cp_commit() {
    asm volatile("cp.async.commit_group;\n" ::: "memory");
}
template <int N>
static __device__ __forceinline__ void cp_wait() {
    asm volatile("cp.async.wait_group %0;\n" :: "n"(N) : "memory");
}

// ---------------- kernel 1: QKV projection (tf32 MMA, cp.async pipeline)
// Block (0,0,z=0) additionally detects the mask dtype.
__global__ __launch_bounds__(256, 2)
void qkv_gemm_tc(const float* __restrict__ x,
                 const float* __restrict__ Wq,
                 const float* __restrict__ Wk,
                 const float* __restrict__ Wv,
                 const unsigned* __restrict__ maskw) {
    __shared__ unsigned As[2][128 * 36];
    __shared__ unsigned Bs[2][128 * 36];

    const int z = blockIdx.z;

    if (z == 0 && blockIdx.x == 0 && blockIdx.y == 0) {
        int gt1 = 0, f32 = 0;
        for (int t = threadIdx.x; t < 4096; t += 256) {
            unsigned v = maskw[t];
            if (v == 0x3F800000u) f32 = 1;
            else if (v > 1u) gt1 = 1;
        }
        gt1 = __syncthreads_or(gt1);
        f32 = __syncthreads_or(f32);
        if (threadIdx.x == 0) g_maskType = f32 ? 2 : (gt1 ? 0 : 1);
    }

    const float* __restrict__ W = (z == 0) ? Wq : (z == 1) ? Wk : Wv;
    float* __restrict__ outp = (z == 0) ? g_Q : (z == 1) ? g_K : g_V;

    const int mBase = blockIdx.x * 128;
    const int nBase = blockIdx.y * 128;
    const int tid = threadIdx.x;
    const int lane = tid & 31;
    const int warp = tid >> 5;
    const int q = lane & 3, r = lane >> 2;
    const int wm = warp & 1, wn = warp >> 1;

    const int srow = tid >> 3;
    const int skq = (tid & 7) * 4;

    auto loadAB = [&](int buf, int k0) {
#pragma unroll
        for (int s = 0; s < 4; s++) {
            int row = srow + 32 * s;
            cp16(&As[buf][row * 36 + skq], &x[(size_t)(mBase + row) * C_DIM + k0 + skq]);
            cp16(&Bs[buf][row * 36 + skq], &W[(size_t)(nBase + row) * C_DIM + k0 + skq]);
        }
    };

    float acc[4][4][4];
#pragma unroll
    for (int mf = 0; mf < 4; mf++)
#pragma unroll
        for (int nf = 0; nf < 4; nf++)
#pragma unroll
            for (int c = 0; c < 4; c++) acc[mf][nf][c] = 0.0f;

    loadAB(0, 0);
    cp_commit();

    for (int step = 0; step < 16; step++) {
        const int cur = step & 1;
        cp_wait<0>();
        __syncthreads();
        if (step < 15) { loadAB(cur ^ 1, (step + 1) * 32); cp_commit(); }

        const unsigned* __restrict__ A = As[cur];
        const unsigned* __restrict__ B = Bs[cur];
#pragma unroll
        for (int ks = 0; ks < 4; ks++) {
            unsigned af[4][4], bf[4][2];
#pragma unroll
            for (int mf = 0; mf < 4; mf++) {
                int rw = wm * 64 + mf * 16 + r;
                af[mf][0] = A[rw * 36 + ks * 8 + q];
                af[mf][1] = A[(rw + 8) * 36 + ks * 8 + q];
                af[mf][2] = A[rw * 36 + ks * 8 + q + 4];
                af[mf][3] = A[(rw + 8) * 36 + ks * 8 + q + 4];
            }
#pragma unroll
            for (int nf = 0; nf < 4; nf++) {
                int cn = wn * 32 + nf * 8 + r;
                bf[nf][0] = B[cn * 36 + ks * 8 + q];
                bf[nf][1] = B[cn * 36 + ks * 8 + q + 4];
            }
#pragma unroll
            for (int mf = 0; mf < 4; mf++)
#pragma unroll
                for (int nf = 0; nf < 4; nf++)
                    mma_tf32(acc[mf][nf], af[mf], bf[nf], acc[mf][nf]);
        }
    }

    const float sc = (z == 0) ? 0.08838834764831843f : 1.0f;  // 1/sqrt(2*64) into Q
#pragma unroll
    for (int mf = 0; mf < 4; mf++) {
        int mG = mBase + wm * 64 + mf * 16 + r;
#pragma unroll
        for (int nf = 0; nf < 4; nf++) {
            int nG = nBase + wn * 32 + nf * 8 + 2 * q;
            int h = nG >> 6, d = nG & 63;
            {
                int bb = mG >> 10, ii = mG & 1023;
                float2 v = { acc[mf][nf][0] * sc, acc[mf][nf][1] * sc };
                *(float2*)&outp[(((size_t)(bb * NH + h) * NA + ii) * D_DIM) + d] = v;
            }
            {
                int mG2 = mG + 8;
                int bb = mG2 >> 10, ii = mG2 & 1023;
                float2 v = { acc[mf][nf][2] * sc, acc[mf][nf][3] * sc };
                *(float2*)&outp[(((size_t)(bb * NH + h) * NA + ii) * D_DIM) + d] = v;
            }
        }
    }
}

// ---------------- kernel 2: fused flash attention ----------------
// grid (NH, NA/128, NB). 256 thr = 8 warps; warp w owns query rows w*16..+15.
// S = Q@K^T (tf32, adj seeded as MMA C); PV in fp16 (m16n8k16) with P packed
// from the S accumulator registers (FA2 layout identity — no smem round trip).
// V staged raw (single buffer, cp.async) then transposed to fp16 Vt[d][j] per tile.
__global__ __launch_bounds__(256, 2)
void flash_tc(const float* __restrict__ adj, const void* __restrict__ mask,
              const float* __restrict__ x, float* __restrict__ out) {
    extern __shared__ unsigned sm[];
    unsigned* Kb   = sm;                          // 2 x 64*68 (tf32 bits)
    unsigned* Vraw = sm + 2 * 64 * 68;            // 64*68 fp32 bits
    __half*   VtH  = (__half*)(sm + 2 * 64 * 68 + 64 * 68);  // 64 x 72 halves

    const int h = blockIdx.x, iT = blockIdx.y, b = blockIdx.z;
    const int tid = threadIdx.x;
    const int lane = tid & 31;
    const int w = tid >> 5;
    const int q = lane & 3, r = lane >> 2;
    const int w16 = w * 16;

    const float* __restrict__ Qp = g_Q + (size_t)(b * NH + h) * NA * D_DIM;
    const float* __restrict__ Kp = g_K + (size_t)(b * NH + h) * NA * D_DIM;
    const float* __restrict__ Vp = g_V + (size_t)(b * NH + h) * NA * D_DIM;

    auto loadK = [&](int buf, int jt) {
        unsigned* Kd = Kb + buf * (64 * 68);
#pragma unroll
        for (int s = 0; s < 4; s++) {
            int slot = s * 256 + tid;
            int row = slot >> 4, cq = (slot & 15) * 4;
            cp16(&Kd[row * 68 + cq], &Kp[(size_t)(jt * 64 + row) * D_DIM + cq]);
        }
    };
    auto loadV = [&](int jt) {
#pragma unroll
        for (int s = 0; s < 4; s++) {
            int slot = s * 256 + tid;
            int row = slot >> 4, cq = (slot & 15) * 4;
            cp16(&Vraw[row * 68 + cq], &Vp[(size_t)(jt * 64 + row) * D_DIM + cq]);
        }
    };

    loadK(0, 0);
    loadV(0);
    cp_commit();

    // Q fragments straight from gmem (once per block)
    const int iG0 = iT * 128 + w16 + r;    // rows iG0 and iG0+8
    unsigned qf[8][4];
    {
        const float* Q0 = Qp + (size_t)(iT * 128 + w16) * D_DIM;
#pragma unroll
        for (int kf = 0; kf < 8; kf++) {
            qf[kf][0] = __float_as_uint(Q0[(size_t)r * D_DIM + kf * 8 + q]);
            qf[kf][1] = __float_as_uint(Q0[(size_t)(r + 8) * D_DIM + kf * 8 + q]);
            qf[kf][2] = __float_as_uint(Q0[(size_t)r * D_DIM + kf * 8 + q + 4]);
            qf[kf][3] = __float_as_uint(Q0[(size_t)(r + 8) * D_DIM + kf * 8 + q + 4]);
        }
    }

    float accO[8][4];
#pragma unroll
    for (int nf = 0; nf < 8; nf++)
#pragma unroll
        for (int c = 0; c < 4; c++) accO[nf][c] = 0.0f;

    float m0 = -3.0e38f, m1 = -3.0e38f, l0 = 0.0f, l1 = 0.0f;
    const int mt = g_maskType;

    const int td = tid & 63;          // transpose: this thread's d column
    const int tjb = (tid >> 6) * 16;  // and 16-j slab

    for (int jt = 0; jt < NA / 64; jt++) {
        const int cur = jt & 1;

        // ---- prefetch adj -> sa (MMA C-init), mask -> codes, before pipeline wait ----
        float sa[8][4];
        unsigned pre[8];
#pragma unroll
        for (int nf = 0; nf < 8; nf++) {
            int jG = jt * 64 + nf * 8 + 2 * q;
            size_t o0 = ((size_t)b * NA + iG0) * NA + jG;
            size_t o1 = o0 + (size_t)8 * NA;
            float2 a0 = *(const float2*)&adj[o0];
            float2 a1 = *(const float2*)&adj[o1];
            sa[nf][0] = a0.x; sa[nf][1] = a0.y;
            sa[nf][2] = a1.x; sa[nf][3] = a1.y;
            unsigned p = 0;
            if (mt == 0) {
                uint16_t w0 = *(const uint16_t*)((const uint8_t*)mask + o0);
                uint16_t w1 = *(const uint16_t*)((const uint8_t*)mask + o1);
                p = (w0 & 0x00FF ? 1u : 0u) | (w0 & 0xFF00 ? 2u : 0u) |
                    (w1 & 0x00FF ? 4u : 0u) | (w1 & 0xFF00 ? 8u : 0u);
            } else if (mt == 1) {
                int2 z0 = *(const int2*)((const int*)mask + o0);
                int2 z1 = *(const int2*)((const int*)mask + o1);
                p = (z0.x ? 1u : 0u) | (z0.y ? 2u : 0u) | (z1.x ? 4u : 0u) | (z1.y ? 8u : 0u);
            } else {
                float2 z0 = *(const float2*)((const float*)mask + o0);
                float2 z1 = *(const float2*)((const float*)mask + o1);
                p = (z0.x != 0.0f ? 1u : 0u) | (z0.y != 0.0f ? 2u : 0u) |
                    (z1.x != 0.0f ? 4u : 0u) | (z1.y != 0.0f ? 8u : 0u);
            }
            pre[nf] = p;
        }

        cp_wait<0>();
        __syncthreads();               // K[cur]/Vraw landed; all warps done with prev tile

        // ---- transpose+convert Vraw[j][d] -> VtH[d][j] (fp16) ----
#pragma unroll
        for (int k = 0; k < 16; k += 2) {
            float v0 = __uint_as_float(Vraw[(tjb + k) * 68 + td]);
            float v1 = __uint_as_float(Vraw[(tjb + k + 1) * 68 + td]);
            *(__half2*)&VtH[td * 72 + tjb + k] = __floats2half2_rn(v0, v1);
        }
        __syncthreads();               // Vt ready; Vraw free for next prefetch

        if (jt + 1 < NA / 64) { loadK(cur ^ 1, jt + 1); loadV(jt + 1); cp_commit(); }

        const unsigned* __restrict__ Ks = Kb + cur * (64 * 68);

        // --- S = Q @ K^T + adj (tf32) ---
#pragma unroll
        for (int nf = 0; nf < 8; nf++) {
            const unsigned* krow = &Ks[(nf * 8 + r) * 68];
#pragma unroll
            for (int kf = 0; kf < 8; kf++) {
                unsigned bf[2] = { krow[kf * 8 + q], krow[kf * 8 + q + 4] };
                mma_tf32(sa[nf], qf[kf], bf, sa[nf]);
            }
        }

        // --- mask ---
#pragma unroll
        for (int nf = 0; nf < 8; nf++) {
            unsigned p = pre[nf];
            if (p & 1u) sa[nf][0] = -1.0e30f;
            if (p & 2u) sa[nf][1] = -1.0e30f;
            if (p & 4u) sa[nf][2] = -1.0e30f;
            if (p & 8u) sa[nf][3] = -1.0e30f;
        }

        // --- online softmax (rows iG0, iG0+8) ---
        float mx0 = -3.0e38f, mx1 = -3.0e38f;
#pragma unroll
        for (int nf = 0; nf < 8; nf++) {
            mx0 = fmaxf(mx0, fmaxf(sa[nf][0], sa[nf][1]));
            mx1 = fmaxf(mx1, fmaxf(sa[nf][2], sa[nf][3]));
        }
        mx0 = fmaxf(mx0, __shfl_xor_sync(0xFFFFFFFFu, mx0, 1));
        mx0 = fmaxf(mx0, __shfl_xor_sync(0xFFFFFFFFu, mx0, 2));
        mx1 = fmaxf(mx1, __shfl_xor_sync(0xFFFFFFFFu, mx1, 1));
        mx1 = fmaxf(mx1, __shfl_xor_sync(0xFFFFFFFFu, mx1, 2));

        float mn0 = fmaxf(m0, mx0), mn1 = fmaxf(m1, mx1);
        float sc0 = __expf(m0 - mn0), sc1 = __expf(m1 - mn1);
        m0 = mn0; m1 = mn1;

        float p0 = 0.0f, p1 = 0.0f;
#pragma unroll
        for (int nf = 0; nf < 8; nf++) {
            sa[nf][0] = __expf(sa[nf][0] - mn0); p0 += sa[nf][0];
            sa[nf][1] = __expf(sa[nf][1] - mn0); p0 += sa[nf][1];
            sa[nf][2] = __expf(sa[nf][2] - mn1); p1 += sa[nf][2];
            sa[nf][3] = __expf(sa[nf][3] - mn1); p1 += sa[nf][3];
        }
        p0 += __shfl_xor_sync(0xFFFFFFFFu, p0, 1);
        p0 += __shfl_xor_sync(0xFFFFFFFFu, p0, 2);
        p1 += __shfl_xor_sync(0xFFFFFFFFu, p1, 1);
        p1 += __shfl_xor_sync(0xFFFFFFFFu, p1, 2);
        l0 = l0 * sc0 + p0;
        l1 = l1 * sc1 + p1;

#pragma unroll
        for (int nf = 0; nf < 8; nf++) {
            accO[nf][0] *= sc0; accO[nf][1] *= sc0;
            accO[nf][2] *= sc1; accO[nf][3] *= sc1;
        }

        // --- pack P accumulators -> fp16 A fragments (registers only) ---
        unsigned ph[8][2];
#pragma unroll
        for (int nf = 0; nf < 8; nf++) {
            ph[nf][0] = packh2(sa[nf][0], sa[nf][1]);   // rows r,   cols nf*8+2q..+1
            ph[nf][1] = packh2(sa[nf][2], sa[nf][3]);   // rows r+8
        }

        // --- PV: m16n8k16 fp16, B from Vt[d][j] ---
#pragma unroll
        for (int t = 0; t < 4; t++) {
            unsigned pa[4] = { ph[2 * t][0], ph[2 * t][1],
                               ph[2 * t + 1][0], ph[2 * t + 1][1] };
#pragma unroll
            for (int nf = 0; nf < 8; nf++) {
                const __half* vrow = &VtH[(nf * 8 + r) * 72 + t * 16 + 2 * q];
                unsigned bf[2] = { *(const unsigned*)&vrow[0],
                                   *(const unsigned*)&vrow[8] };
                mma_f16(accO[nf], pa, bf);
            }
        }
    }

    // --- epilogue: out = accO / l + x ---
    float li0 = 1.0f / l0, li1 = 1.0f / l1;
#pragma unroll
    for (int nf = 0; nf < 8; nf++) {
        int cG = h * 64 + nf * 8 + 2 * q;
        size_t o0 = ((size_t)(b * NA + iG0)) * C_DIM + cG;
        size_t o1 = ((size_t)(b * NA + iG0 + 8)) * C_DIM + cG;
        float2 x0 = *(const float2*)&x[o0];
        float2 x1 = *(const float2*)&x[o1];
        float2 r0 = { accO[nf][0] * li0 + x0.x, accO[nf][1] * li0 + x0.y };
        float2 r1 = { accO[nf][2] * li1 + x1.x, accO[nf][3] * li1 + x1.y };
        *(float2*)&out[o0] = r0;
        *(float2*)&out[o1] = r1;
    }
}

// ---------------- launch ----------------
#define SMEM_FLASH ((2 * 64 * 68 + 64 * 68 + 64 * 36) * 4)

extern "C" void kernel_launch(void* const* d_in, const int* in_sizes, int n_in,
                              void* d_out, int out_size) {
    const float* x    = (const float*)d_in[0];
    const void*  mask = d_in[1];
    const float* adj  = (const float*)d_in[2];
    const float* Wq   = (const float*)d_in[3];
    const float* Wk   = (const float*)d_in[4];
    const float* Wv   = (const float*)d_in[5];
    float* out = (float*)d_out;

    dim3 g1(NB * NA / 128, C_DIM / 128, 3);
    qkv_gemm_tc<<<g1, 256>>>(x, Wq, Wk, Wv, (const unsigned*)mask);

    cudaFuncSetAttribute(flash_tc, cudaFuncAttributeMaxDynamicSharedMemorySize, SMEM_FLASH);
    dim3 g2(NH, NA / 128, NB);
    flash_tc<<<g2, 256, SMEM_FLASH>>>(adj, mask, x, out);
}

// round 6
// speedup vs baseline: 3.4860x; 1.1022x over previous
#include <cuda_runtime.h>
#include <cuda_fp16.h>
#include <cstdint>
#include <cstddef>

#define NB 16
#define NA 1024
#define C_DIM 512
#define NH 8
#define D_DIM 64

// ---------------- device scratch ----------------
__device__ __half g_Qh[(size_t)NB * NH * NA * D_DIM];  // [b][h][i][d], pre-scaled by 1/TP
__device__ __half g_Kh[(size_t)NB * NH * NA * D_DIM];
__device__ __half g_Vh[(size_t)NB * NH * NA * D_DIM];
__device__ int    g_maskType;                          // 0=u8, 1=i32, 2=f32

// ---------------- helpers ----------------
static __device__ __forceinline__ void mma_tf32(float* d, const unsigned* a,
                                                const unsigned* b, const float* c) {
    asm volatile(
        "mma.sync.aligned.m16n8k8.row.col.f32.tf32.tf32.f32 "
        "{%0,%1,%2,%3}, {%4,%5,%6,%7}, {%8,%9}, {%10,%11,%12,%13};"
        : "=f"(d[0]), "=f"(d[1]), "=f"(d[2]), "=f"(d[3])
        : "r"(a[0]), "r"(a[1]), "r"(a[2]), "r"(a[3]),
          "r"(b[0]), "r"(b[1]),
          "f"(c[0]), "f"(c[1]), "f"(c[2]), "f"(c[3]));
}

static __device__ __forceinline__ void mma_f16(float* d, const unsigned* a,
                                               const unsigned* b) {
    asm volatile(
        "mma.sync.aligned.m16n8k16.row.col.f32.f16.f16.f32 "
        "{%0,%1,%2,%3}, {%4,%5,%6,%7}, {%8,%9}, {%0,%1,%2,%3};"
        : "+f"(d[0]), "+f"(d[1]), "+f"(d[2]), "+f"(d[3])
        : "r"(a[0]), "r"(a[1]), "r"(a[2]), "r"(a[3]),
          "r"(b[0]), "r"(b[1]));
}

static __device__ __forceinline__ unsigned packh2(float lo, float hi) {
    __half2 h = __floats2half2_rn(lo, hi);
    return *(unsigned*)&h;
}

static __device__ __forceinline__ void cp16(void* smem, const void* g) {
    unsigned saddr = (unsigned)__cvta_generic_to_shared(smem);
    asm volatile("cp.async.cg.shared.global [%0], [%1], 16;\n" :: "r"(saddr), "l"(g));
}
static __device__ __forceinline__ void cp_commit() {
    asm volatile("cp.async.commit_group;\n" ::: "memory");
}
template <int N>
static __device__ __forceinline__ void cp_wait() {
    asm volatile("cp.async.wait_group %0;\n" :: "n"(N) : "memory");
}

// ---------------- kernel 1: QKV projection (tf32 MMA, cp.async pipeline) ----------------
// Outputs fp16 Q/K/V in [b][h][i][d]; Q pre-scaled by 1/TP.
// Block (0,0,z=0) additionally detects the mask dtype.
__global__ __launch_bounds__(256, 2)
void qkv_gemm_tc(const float* __restrict__ x,
                 const float* __restrict__ Wq,
                 const float* __restrict__ Wk,
                 const float* __restrict__ Wv,
                 const unsigned* __restrict__ maskw) {
    __shared__ unsigned As[2][128 * 36];
    __shared__ unsigned Bs[2][128 * 36];

    const int z = blockIdx.z;

    if (z == 0 && blockIdx.x == 0 && blockIdx.y == 0) {
        int gt1 = 0, f32 = 0;
        for (int t = threadIdx.x; t < 4096; t += 256) {
            unsigned v = maskw[t];
            if (v == 0x3F800000u) f32 = 1;
            else if (v > 1u) gt1 = 1;
        }
        gt1 = __syncthreads_or(gt1);
        f32 = __syncthreads_or(f32);
        if (threadIdx.x == 0) g_maskType = f32 ? 2 : (gt1 ? 0 : 1);
    }

    const float* __restrict__ W = (z == 0) ? Wq : (z == 1) ? Wk : Wv;
    __half* __restrict__ outp = (z == 0) ? g_Qh : (z == 1) ? g_Kh : g_Vh;

    const int mBase = blockIdx.x * 128;
    const int nBase = blockIdx.y * 128;
    const int tid = threadIdx.x;
    const int lane = tid & 31;
    const int warp = tid >> 5;
    const int q = lane & 3, r = lane >> 2;
    const int wm = warp & 1, wn = warp >> 1;

    const int srow = tid >> 3;
    const int skq = (tid & 7) * 4;

    auto loadAB = [&](int buf, int k0) {
#pragma unroll
        for (int s = 0; s < 4; s++) {
            int row = srow + 32 * s;
            cp16(&As[buf][row * 36 + skq], &x[(size_t)(mBase + row) * C_DIM + k0 + skq]);
            cp16(&Bs[buf][row * 36 + skq], &W[(size_t)(nBase + row) * C_DIM + k0 + skq]);
        }
    };

    float acc[4][4][4];
#pragma unroll
    for (int mf = 0; mf < 4; mf++)
#pragma unroll
        for (int nf = 0; nf < 4; nf++)
#pragma unroll
            for (int c = 0; c < 4; c++) acc[mf][nf][c] = 0.0f;

    loadAB(0, 0);
    cp_commit();

    for (int step = 0; step < 16; step++) {
        const int cur = step & 1;
        cp_wait<0>();
        __syncthreads();
        if (step < 15) { loadAB(cur ^ 1, (step + 1) * 32); cp_commit(); }

        const unsigned* __restrict__ A = As[cur];
        const unsigned* __restrict__ B = Bs[cur];
#pragma unroll
        for (int ks = 0; ks < 4; ks++) {
            unsigned af[4][4], bf[4][2];
#pragma unroll
            for (int mf = 0; mf < 4; mf++) {
                int rw = wm * 64 + mf * 16 + r;
                af[mf][0] = A[rw * 36 + ks * 8 + q];
                af[mf][1] = A[(rw + 8) * 36 + ks * 8 + q];
                af[mf][2] = A[rw * 36 + ks * 8 + q + 4];
                af[mf][3] = A[(rw + 8) * 36 + ks * 8 + q + 4];
            }
#pragma unroll
            for (int nf = 0; nf < 4; nf++) {
                int cn = wn * 32 + nf * 8 + r;
                bf[nf][0] = B[cn * 36 + ks * 8 + q];
                bf[nf][1] = B[cn * 36 + ks * 8 + q + 4];
            }
#pragma unroll
            for (int mf = 0; mf < 4; mf++)
#pragma unroll
                for (int nf = 0; nf < 4; nf++)
                    mma_tf32(acc[mf][nf], af[mf], bf[nf], acc[mf][nf]);
        }
    }

    const float sc = (z == 0) ? 0.08838834764831843f : 1.0f;  // 1/sqrt(2*64) into Q
#pragma unroll
    for (int mf = 0; mf < 4; mf++) {
        int mG = mBase + wm * 64 + mf * 16 + r;
#pragma unroll
        for (int nf = 0; nf < 4; nf++) {
            int nG = nBase + wn * 32 + nf * 8 + 2 * q;
            int h = nG >> 6, d = nG & 63;
            {
                int bb = mG >> 10, ii = mG & 1023;
                __half2 v = __floats2half2_rn(acc[mf][nf][0] * sc, acc[mf][nf][1] * sc);
                *(__half2*)&outp[(((size_t)(bb * NH + h) * NA + ii) * D_DIM) + d] = v;
            }
            {
                int mG2 = mG + 8;
                int bb = mG2 >> 10, ii = mG2 & 1023;
                __half2 v = __floats2half2_rn(acc[mf][nf][2] * sc, acc[mf][nf][3] * sc);
                *(__half2*)&outp[(((size_t)(bb * NH + h) * NA + ii) * D_DIM) + d] = v;
            }
        }
    }
}

// ---------------- kernel 2: fused flash attention (all-fp16 operands) ----------------
// grid (NH, NA/128, NB). 256 thr = 8 warps; warp w owns query rows w*16..+15.
// S = Q@K^T (fp16 m16n8k16, adj seeded as MMA C, fp32 accum); online softmax;
// PV fp16 with P packed from S accumulators (FA2 identity). K double-buffered fp16
// via cp.async; V staged fp16 then transposed to Vt[d][j] per tile.
__global__ __launch_bounds__(256, 2)
void flash_tc(const float* __restrict__ adj, const void* __restrict__ mask,
              const float* __restrict__ x, float* __restrict__ out) {
    extern __shared__ __half smh[];
    __half* Kb   = smh;                    // 2 x 64*72 fp16
    __half* Vraw = smh + 2 * 64 * 72;      // 64*72 fp16
    __half* VtH  = Vraw + 64 * 72;         // 64*72 fp16, [d][j]

    const int h = blockIdx.x, iT = blockIdx.y, b = blockIdx.z;
    const int tid = threadIdx.x;
    const int lane = tid & 31;
    const int w = tid >> 5;
    const int q = lane & 3, r = lane >> 2;
    const int w16 = w * 16;
    const int bh = b * NH + h;

    const __half* __restrict__ Qp = g_Qh + (size_t)bh * NA * D_DIM;
    const __half* __restrict__ Kp = g_Kh + (size_t)bh * NA * D_DIM;
    const __half* __restrict__ Vp = g_Vh + (size_t)bh * NA * D_DIM;

    // tile = 64 rows x 64 halves (128B) = 512 x 16B chunks; 2 chunks per thread
    auto loadK = [&](int buf, int jt) {
        __half* Kd = Kb + buf * (64 * 72);
#pragma unroll
        for (int s = 0; s < 2; s++) {
            int slot = s * 256 + tid;
            int row = slot >> 3, ck = (slot & 7) * 8;
            cp16(&Kd[row * 72 + ck], &Kp[(size_t)(jt * 64 + row) * D_DIM + ck]);
        }
    };
    auto loadV = [&](int jt) {
#pragma unroll
        for (int s = 0; s < 2; s++) {
            int slot = s * 256 + tid;
            int row = slot >> 3, ck = (slot & 7) * 8;
            cp16(&Vraw[row * 72 + ck], &Vp[(size_t)(jt * 64 + row) * D_DIM + ck]);
        }
    };

    loadK(0, 0);
    loadV(0);
    cp_commit();

    // Q fragments (fp16 A frags for m16n8k16) straight from gmem, once per block
    const int iG0 = iT * 128 + w16 + r;    // rows iG0 and iG0+8
    unsigned qa[4][4];
    {
        const __half* Q0 = Qp + (size_t)(iT * 128 + w16) * D_DIM;
#pragma unroll
        for (int t = 0; t < 4; t++) {
            qa[t][0] = *(const unsigned*)&Q0[(size_t)r * D_DIM + t * 16 + 2 * q];
            qa[t][1] = *(const unsigned*)&Q0[(size_t)(r + 8) * D_DIM + t * 16 + 2 * q];
            qa[t][2] = *(const unsigned*)&Q0[(size_t)r * D_DIM + t * 16 + 2 * q + 8];
            qa[t][3] = *(const unsigned*)&Q0[(size_t)(r + 8) * D_DIM + t * 16 + 2 * q + 8];
        }
    }

    float accO[8][4];
#pragma unroll
    for (int nf = 0; nf < 8; nf++)
#pragma unroll
        for (int c = 0; c < 4; c++) accO[nf][c] = 0.0f;

    float m0 = -3.0e38f, m1 = -3.0e38f, l0 = 0.0f, l1 = 0.0f;
    const int mt = g_maskType;

    const int td = tid & 63;          // transpose: this thread's d column
    const int tjb = (tid >> 6) * 16;  // and 16-j slab

    for (int jt = 0; jt < NA / 64; jt++) {
        const int cur = jt & 1;

        // ---- prefetch adj -> sa (MMA C-init), mask -> codes, before pipeline wait ----
        float sa[8][4];
        unsigned pre[8];
#pragma unroll
        for (int nf = 0; nf < 8; nf++) {
            int jG = jt * 64 + nf * 8 + 2 * q;
            size_t o0 = ((size_t)b * NA + iG0) * NA + jG;
            size_t o1 = o0 + (size_t)8 * NA;
            float2 a0 = *(const float2*)&adj[o0];
            float2 a1 = *(const float2*)&adj[o1];
            sa[nf][0] = a0.x; sa[nf][1] = a0.y;
            sa[nf][2] = a1.x; sa[nf][3] = a1.y;
            unsigned p = 0;
            if (mt == 0) {
                uint16_t w0 = *(const uint16_t*)((const uint8_t*)mask + o0);
                uint16_t w1 = *(const uint16_t*)((const uint8_t*)mask + o1);
                p = (w0 & 0x00FF ? 1u : 0u) | (w0 & 0xFF00 ? 2u : 0u) |
                    (w1 & 0x00FF ? 4u : 0u) | (w1 & 0xFF00 ? 8u : 0u);
            } else if (mt == 1) {
                int2 z0 = *(const int2*)((const int*)mask + o0);
                int2 z1 = *(const int2*)((const int*)mask + o1);
                p = (z0.x ? 1u : 0u) | (z0.y ? 2u : 0u) | (z1.x ? 4u : 0u) | (z1.y ? 8u : 0u);
            } else {
                float2 z0 = *(const float2*)((const float*)mask + o0);
                float2 z1 = *(const float2*)((const float*)mask + o1);
                p = (z0.x != 0.0f ? 1u : 0u) | (z0.y != 0.0f ? 2u : 0u) |
                    (z1.x != 0.0f ? 4u : 0u) | (z1.y != 0.0f ? 8u : 0u);
            }
            pre[nf] = p;
        }

        cp_wait<0>();
        __syncthreads();               // K[cur]/Vraw landed; all warps done with prev tile

        // ---- transpose Vraw[j][d] -> VtH[d][j] ----
#pragma unroll
        for (int k = 0; k < 16; k += 2) {
            __half v0 = Vraw[(tjb + k) * 72 + td];
            __half v1 = Vraw[(tjb + k + 1) * 72 + td];
            *(__half2*)&VtH[td * 72 + tjb + k] = __halves2half2(v0, v1);
        }
        __syncthreads();               // Vt ready; Vraw free for next prefetch

        if (jt + 1 < NA / 64) { loadK(cur ^ 1, jt + 1); loadV(jt + 1); cp_commit(); }

        const __half* __restrict__ Ks = Kb + cur * (64 * 72);

        // --- S = Q @ K^T + adj (fp16 MMA, fp32 accum) ---
#pragma unroll
        for (int t = 0; t < 4; t++) {
#pragma unroll
            for (int nf = 0; nf < 8; nf++) {
                const __half* krow = &Ks[(nf * 8 + r) * 72 + t * 16 + 2 * q];
                unsigned bf[2] = { *(const unsigned*)&krow[0],
                                   *(const unsigned*)&krow[8] };
                mma_f16(sa[nf], qa[t], bf);
            }
        }

        // --- mask ---
#pragma unroll
        for (int nf = 0; nf < 8; nf++) {
            unsigned p = pre[nf];
            if (p & 1u) sa[nf][0] = -1.0e30f;
            if (p & 2u) sa[nf][1] = -1.0e30f;
            if (p & 4u) sa[nf][2] = -1.0e30f;
            if (p & 8u) sa[nf][3] = -1.0e30f;
        }

        // --- online softmax (rows iG0, iG0+8) ---
        float mx0 = -3.0e38f, mx1 = -3.0e38f;
#pragma unroll
        for (int nf = 0; nf < 8; nf++) {
            mx0 = fmaxf(mx0, fmaxf(sa[nf][0], sa[nf][1]));
            mx1 = fmaxf(mx1, fmaxf(sa[nf][2], sa[nf][3]));
        }
        mx0 = fmaxf(mx0, __shfl_xor_sync(0xFFFFFFFFu, mx0, 1));
        mx0 = fmaxf(mx0, __shfl_xor_sync(0xFFFFFFFFu, mx0, 2));
        mx1 = fmaxf(mx1, __shfl_xor_sync(0xFFFFFFFFu, mx1, 1));
        mx1 = fmaxf(mx1, __shfl_xor_sync(0xFFFFFFFFu, mx1, 2));

        float mn0 = fmaxf(m0, mx0), mn1 = fmaxf(m1, mx1);
        float sc0 = __expf(m0 - mn0), sc1 = __expf(m1 - mn1);
        m0 = mn0; m1 = mn1;

        float p0 = 0.0f, p1 = 0.0f;
#pragma unroll
        for (int nf = 0; nf < 8; nf++) {
            sa[nf][0] = __expf(sa[nf][0] - mn0); p0 += sa[nf][0];
            sa[nf][1] = __expf(sa[nf][1] - mn0); p0 += sa[nf][1];
            sa[nf][2] = __expf(sa[nf][2] - mn1); p1 += sa[nf][2];
            sa[nf][3] = __expf(sa[nf][3] - mn1); p1 += sa[nf][3];
        }
        p0 += __shfl_xor_sync(0xFFFFFFFFu, p0, 1);
        p0 += __shfl_xor_sync(0xFFFFFFFFu, p0, 2);
        p1 += __shfl_xor_sync(0xFFFFFFFFu, p1, 1);
        p1 += __shfl_xor_sync(0xFFFFFFFFu, p1, 2);
        l0 = l0 * sc0 + p0;
        l1 = l1 * sc1 + p1;

#pragma unroll
        for (int nf = 0; nf < 8; nf++) {
            accO[nf][0] *= sc0; accO[nf][1] *= sc0;
            accO[nf][2] *= sc1; accO[nf][3] *= sc1;
        }

        // --- pack P accumulators -> fp16 A fragments (registers only) ---
        unsigned ph[8][2];
#pragma unroll
        for (int nf = 0; nf < 8; nf++) {
            ph[nf][0] = packh2(sa[nf][0], sa[nf][1]);   // row r
            ph[nf][1] = packh2(sa[nf][2], sa[nf][3]);   // row r+8
        }

        // --- PV: m16n8k16 fp16, B from Vt[d][j] ---
#pragma unroll
        for (int t = 0; t < 4; t++) {
            unsigned pa[4] = { ph[2 * t][0], ph[2 * t][1],
                               ph[2 * t + 1][0], ph[2 * t + 1][1] };
#pragma unroll
            for (int nf = 0; nf < 8; nf++) {
                const __half* vrow = &VtH[(nf * 8 + r) * 72 + t * 16 + 2 * q];
                unsigned bf[2] = { *(const unsigned*)&vrow[0],
                                   *(const unsigned*)&vrow[8] };
                mma_f16(accO[nf], pa, bf);
            }
        }
    }

    // --- epilogue: out = accO / l + x ---
    float li0 = 1.0f / l0, li1 = 1.0f / l1;
#pragma unroll
    for (int nf = 0; nf < 8; nf++) {
        int cG = h * 64 + nf * 8 + 2 * q;
        size_t o0 = ((size_t)(b * NA + iG0)) * C_DIM + cG;
        size_t o1 = ((size_t)(b * NA + iG0 + 8)) * C_DIM + cG;
        float2 x0 = *(const float2*)&x[o0];
        float2 x1 = *(const float2*)&x[o1];
        float2 r0 = { accO[nf][0] * li0 + x0.x, accO[nf][1] * li0 + x0.y };
        float2 r1 = { accO[nf][2] * li1 + x1.x, accO[nf][3] * li1 + x1.y };
        *(float2*)&out[o0] = r0;
        *(float2*)&out[o1] = r1;
    }
}

// ---------------- launch ----------------
#define SMEM_FLASH ((2 * 64 * 72 + 2 * 64 * 72) * 2)   // K(2) + Vraw + Vt, fp16

extern "C" void kernel_launch(void* const* d_in, const int* in_sizes, int n_in,
                              void* d_out, int out_size) {
    const float* x    = (const float*)d_in[0];
    const void*  mask = d_in[1];
    const float* adj  = (const float*)d_in[2];
    const float* Wq   = (const float*)d_in[3];
    const float* Wk   = (const float*)d_in[4];
    const float* Wv   = (const float*)d_in[5];
    float* out = (float*)d_out;

    dim3 g1(NB * NA / 128, C_DIM / 128, 3);
    qkv_gemm_tc<<<g1, 256>>>(x, Wq, Wk, Wv, (const unsigned*)mask);

    cudaFuncSetAttribute(flash_tc, cudaFuncAttributeMaxDynamicSharedMemorySize, SMEM_FLASH);
    dim3 g2(NH, NA / 128, NB);
    flash_tc<<<g2, 256, SMEM_FLASH>>>(adj, mask, x, out);
}

// round 7
// speedup vs baseline: 3.7163x; 1.0661x over previous
#include <cuda_runtime.h>
#include <cuda_fp16.h>
#include <cstdint>
#include <cstddef>

#define NB 16
#define NA 1024
#define C_DIM 512
#define NH 8
#define D_DIM 64

// ---------------- device scratch ----------------
__device__ __half g_Qh[(size_t)NB * NH * NA * D_DIM];  // [b][h][i][d], pre-scaled by 1/TP
__device__ __half g_Kh[(size_t)NB * NH * NA * D_DIM];
__device__ __half g_Vh[(size_t)NB * NH * NA * D_DIM];
__device__ int    g_maskType;                          // 0=u8, 1=i32, 2=f32

// ---------------- helpers ----------------
static __device__ __forceinline__ void mma_tf32(float* d, const unsigned* a,
                                                const unsigned* b, const float* c) {
    asm volatile(
        "mma.sync.aligned.m16n8k8.row.col.f32.tf32.tf32.f32 "
        "{%0,%1,%2,%3}, {%4,%5,%6,%7}, {%8,%9}, {%10,%11,%12,%13};"
        : "=f"(d[0]), "=f"(d[1]), "=f"(d[2]), "=f"(d[3])
        : "r"(a[0]), "r"(a[1]), "r"(a[2]), "r"(a[3]),
          "r"(b[0]), "r"(b[1]),
          "f"(c[0]), "f"(c[1]), "f"(c[2]), "f"(c[3]));
}

static __device__ __forceinline__ void mma_f16(float* d, const unsigned* a,
                                               const unsigned* b) {
    asm volatile(
        "mma.sync.aligned.m16n8k16.row.col.f32.f16.f16.f32 "
        "{%0,%1,%2,%3}, {%4,%5,%6,%7}, {%8,%9}, {%0,%1,%2,%3};"
        : "+f"(d[0]), "+f"(d[1]), "+f"(d[2]), "+f"(d[3])
        : "r"(a[0]), "r"(a[1]), "r"(a[2]), "r"(a[3]),
          "r"(b[0]), "r"(b[1]));
}

static __device__ __forceinline__ void ldsm_x4(unsigned* d, unsigned saddr) {
    asm volatile(
        "ldmatrix.sync.aligned.m8n8.x4.shared.b16 {%0,%1,%2,%3}, [%4];"
        : "=r"(d[0]), "=r"(d[1]), "=r"(d[2]), "=r"(d[3]) : "r"(saddr));
}
static __device__ __forceinline__ void ldsm_x4_trans(unsigned* d, unsigned saddr) {
    asm volatile(
        "ldmatrix.sync.aligned.m8n8.x4.trans.shared.b16 {%0,%1,%2,%3}, [%4];"
        : "=r"(d[0]), "=r"(d[1]), "=r"(d[2]), "=r"(d[3]) : "r"(saddr));
}

static __device__ __forceinline__ unsigned packh2(float lo, float hi) {
    __half2 h = __floats2half2_rn(lo, hi);
    return *(unsigned*)&h;
}

static __device__ __forceinline__ void cp16(void* smem, const void* g) {
    unsigned saddr = (unsigned)__cvta_generic_to_shared(smem);
    asm volatile("cp.async.cg.shared.global [%0], [%1], 16;\n" :: "r"(saddr), "l"(g));
}
static __device__ __forceinline__ void cp_commit() {
    asm volatile("cp.async.commit_group;\n" ::: "memory");
}
template <int N>
static __device__ __forceinline__ void cp_wait() {
    asm volatile("cp.async.wait_group %0;\n" :: "n"(N) : "memory");
}

// ---------------- kernel 1: QKV projection (tf32 MMA, cp.async pipeline) ----------------
// Outputs fp16 Q/K/V in [b][h][i][d]; Q pre-scaled by 1/TP.
// Block (0,0,z=0) additionally detects the mask dtype.
__global__ __launch_bounds__(256, 2)
void qkv_gemm_tc(const float* __restrict__ x,
                 const float* __restrict__ Wq,
                 const float* __restrict__ Wk,
                 const float* __restrict__ Wv,
                 const unsigned* __restrict__ maskw) {
    __shared__ unsigned As[2][128 * 36];
    __shared__ unsigned Bs[2][128 * 36];

    const int z = blockIdx.z;

    if (z == 0 && blockIdx.x == 0 && blockIdx.y == 0) {
        int gt1 = 0, f32 = 0;
        for (int t = threadIdx.x; t < 4096; t += 256) {
            unsigned v = maskw[t];
            if (v == 0x3F800000u) f32 = 1;
            else if (v > 1u) gt1 = 1;
        }
        gt1 = __syncthreads_or(gt1);
        f32 = __syncthreads_or(f32);
        if (threadIdx.x == 0) g_maskType = f32 ? 2 : (gt1 ? 0 : 1);
    }

    const float* __restrict__ W = (z == 0) ? Wq : (z == 1) ? Wk : Wv;
    __half* __restrict__ outp = (z == 0) ? g_Qh : (z == 1) ? g_Kh : g_Vh;

    const int mBase = blockIdx.x * 128;
    const int nBase = blockIdx.y * 128;
    const int tid = threadIdx.x;
    const int lane = tid & 31;
    const int warp = tid >> 5;
    const int q = lane & 3, r = lane >> 2;
    const int wm = warp & 1, wn = warp >> 1;

    const int srow = tid >> 3;
    const int skq = (tid & 7) * 4;

    auto loadAB = [&](int buf, int k0) {
#pragma unroll
        for (int s = 0; s < 4; s++) {
            int row = srow + 32 * s;
            cp16(&As[buf][row * 36 + skq], &x[(size_t)(mBase + row) * C_DIM + k0 + skq]);
            cp16(&Bs[buf][row * 36 + skq], &W[(size_t)(nBase + row) * C_DIM + k0 + skq]);
        }
    };

    float acc[4][4][4];
#pragma unroll
    for (int mf = 0; mf < 4; mf++)
#pragma unroll
        for (int nf = 0; nf < 4; nf++)
#pragma unroll
            for (int c = 0; c < 4; c++) acc[mf][nf][c] = 0.0f;

    loadAB(0, 0);
    cp_commit();

    for (int step = 0; step < 16; step++) {
        const int cur = step & 1;
        cp_wait<0>();
        __syncthreads();
        if (step < 15) { loadAB(cur ^ 1, (step + 1) * 32); cp_commit(); }

        const unsigned* __restrict__ A = As[cur];
        const unsigned* __restrict__ B = Bs[cur];
#pragma unroll
        for (int ks = 0; ks < 4; ks++) {
            unsigned af[4][4], bf[4][2];
#pragma unroll
            for (int mf = 0; mf < 4; mf++) {
                int rw = wm * 64 + mf * 16 + r;
                af[mf][0] = A[rw * 36 + ks * 8 + q];
                af[mf][1] = A[(rw + 8) * 36 + ks * 8 + q];
                af[mf][2] = A[rw * 36 + ks * 8 + q + 4];
                af[mf][3] = A[(rw + 8) * 36 + ks * 8 + q + 4];
            }
#pragma unroll
            for (int nf = 0; nf < 4; nf++) {
                int cn = wn * 32 + nf * 8 + r;
                bf[nf][0] = B[cn * 36 + ks * 8 + q];
                bf[nf][1] = B[cn * 36 + ks * 8 + q + 4];
            }
#pragma unroll
            for (int mf = 0; mf < 4; mf++)
#pragma unroll
                for (int nf = 0; nf < 4; nf++)
                    mma_tf32(acc[mf][nf], af[mf], bf[nf], acc[mf][nf]);
        }
    }

    const float sc = (z == 0) ? 0.08838834764831843f : 1.0f;  // 1/sqrt(2*64) into Q
#pragma unroll
    for (int mf = 0; mf < 4; mf++) {
        int mG = mBase + wm * 64 + mf * 16 + r;
#pragma unroll
        for (int nf = 0; nf < 4; nf++) {
            int nG = nBase + wn * 32 + nf * 8 + 2 * q;
            int h = nG >> 6, d = nG & 63;
            {
                int bb = mG >> 10, ii = mG & 1023;
                __half2 v = __floats2half2_rn(acc[mf][nf][0] * sc, acc[mf][nf][1] * sc);
                *(__half2*)&outp[(((size_t)(bb * NH + h) * NA + ii) * D_DIM) + d] = v;
            }
            {
                int mG2 = mG + 8;
                int bb = mG2 >> 10, ii = mG2 & 1023;
                __half2 v = __floats2half2_rn(acc[mf][nf][2] * sc, acc[mf][nf][3] * sc);
                *(__half2*)&outp[(((size_t)(bb * NH + h) * NA + ii) * D_DIM) + d] = v;
            }
        }
    }
}

// ---------------- kernel 2: fused flash attention (fp16, ldmatrix fragments) ----------------
// grid (NH, NA/128, NB). 256 thr = 8 warps; warp w owns query rows w*16..+15.
// S = Q@K^T (fp16 m16n8k16, adj seeded as MMA C); K frags via ldmatrix.x4;
// V frags via ldmatrix.x4.trans straight off the raw [j][d] tile (no transpose pass).
// K and V both double-buffered via cp.async; one __syncthreads per tile.
__global__ __launch_bounds__(256, 2)
void flash_tc(const float* __restrict__ adj, const void* __restrict__ mask,
              const float* __restrict__ x, float* __restrict__ out) {
    extern __shared__ __half smh[];
    __half* Kb = smh;                    // 2 x 64*72 fp16
    __half* Vb = smh + 2 * 64 * 72;      // 2 x 64*72 fp16 (raw [j][d])

    const int h = blockIdx.x, iT = blockIdx.y, b = blockIdx.z;
    const int tid = threadIdx.x;
    const int lane = tid & 31;
    const int w = tid >> 5;
    const int q = lane & 3, r = lane >> 2;
    const int w16 = w * 16;
    const int bh = b * NH + h;

    const __half* __restrict__ Qp = g_Qh + (size_t)bh * NA * D_DIM;
    const __half* __restrict__ Kp = g_Kh + (size_t)bh * NA * D_DIM;
    const __half* __restrict__ Vp = g_Vh + (size_t)bh * NA * D_DIM;

    const unsigned KbS = (unsigned)__cvta_generic_to_shared(Kb);
    const unsigned VbS = (unsigned)__cvta_generic_to_shared(Vb);

    // ldmatrix per-lane source coordinates (halves)
    const int kj = ((lane >> 4) & 1) * 8 + (lane & 7);   // K: j within nf-pair
    const int kd = ((lane >> 3) & 1) * 8;                // K: d lo/hi tile
    const int vj = ((lane >> 3) & 1) * 8 + (lane & 7);   // V: j lo/hi within k-chunk
    const int vd = ((lane >> 4) & 1) * 8;                // V: d lo/hi tile

    // tile = 64 rows x 64 halves = 512 x 16B chunks; 2 chunks per thread
    auto loadK = [&](int buf, int jt) {
        __half* Kd = Kb + buf * (64 * 72);
#pragma unroll
        for (int s = 0; s < 2; s++) {
            int slot = s * 256 + tid;
            int row = slot >> 3, ck = (slot & 7) * 8;
            cp16(&Kd[row * 72 + ck], &Kp[(size_t)(jt * 64 + row) * D_DIM + ck]);
        }
    };
    auto loadV = [&](int buf, int jt) {
        __half* Vd = Vb + buf * (64 * 72);
#pragma unroll
        for (int s = 0; s < 2; s++) {
            int slot = s * 256 + tid;
            int row = slot >> 3, ck = (slot & 7) * 8;
            cp16(&Vd[row * 72 + ck], &Vp[(size_t)(jt * 64 + row) * D_DIM + ck]);
        }
    };

    loadK(0, 0);
    loadV(0, 0);
    cp_commit();

    // Q fragments (fp16 A frags for m16n8k16) straight from gmem, once per block
    const int iG0 = iT * 128 + w16 + r;    // rows iG0 and iG0+8
    unsigned qa[4][4];
    {
        const __half* Q0 = Qp + (size_t)(iT * 128 + w16) * D_DIM;
#pragma unroll
        for (int t = 0; t < 4; t++) {
            qa[t][0] = *(const unsigned*)&Q0[(size_t)r * D_DIM + t * 16 + 2 * q];
            qa[t][1] = *(const unsigned*)&Q0[(size_t)(r + 8) * D_DIM + t * 16 + 2 * q];
            qa[t][2] = *(const unsigned*)&Q0[(size_t)r * D_DIM + t * 16 + 2 * q + 8];
            qa[t][3] = *(const unsigned*)&Q0[(size_t)(r + 8) * D_DIM + t * 16 + 2 * q + 8];
        }
    }

    float accO[8][4];
#pragma unroll
    for (int nf = 0; nf < 8; nf++)
#pragma unroll
        for (int c = 0; c < 4; c++) accO[nf][c] = 0.0f;

    float m0 = -3.0e38f, m1 = -3.0e38f, l0 = 0.0f, l1 = 0.0f;
    const int mt = g_maskType;

    for (int jt = 0; jt < NA / 64; jt++) {
        const int cur = jt & 1;

        // ---- prefetch adj -> sa (MMA C-init), mask -> codes, before pipeline wait ----
        float sa[8][4];
        unsigned pre[8];
#pragma unroll
        for (int nf = 0; nf < 8; nf++) {
            int jG = jt * 64 + nf * 8 + 2 * q;
            size_t o0 = ((size_t)b * NA + iG0) * NA + jG;
            size_t o1 = o0 + (size_t)8 * NA;
            float2 a0 = *(const float2*)&adj[o0];
            float2 a1 = *(const float2*)&adj[o1];
            sa[nf][0] = a0.x; sa[nf][1] = a0.y;
            sa[nf][2] = a1.x; sa[nf][3] = a1.y;
            unsigned p = 0;
            if (mt == 0) {
                uint16_t w0 = *(const uint16_t*)((const uint8_t*)mask + o0);
                uint16_t w1 = *(const uint16_t*)((const uint8_t*)mask + o1);
                p = (w0 & 0x00FF ? 1u : 0u) | (w0 & 0xFF00 ? 2u : 0u) |
                    (w1 & 0x00FF ? 4u : 0u) | (w1 & 0xFF00 ? 8u : 0u);
            } else if (mt == 1) {
                int2 z0 = *(const int2*)((const int*)mask + o0);
                int2 z1 = *(const int2*)((const int*)mask + o1);
                p = (z0.x ? 1u : 0u) | (z0.y ? 2u : 0u) | (z1.x ? 4u : 0u) | (z1.y ? 8u : 0u);
            } else {
                float2 z0 = *(const float2*)((const float*)mask + o0);
                float2 z1 = *(const float2*)((const float*)mask + o1);
                p = (z0.x != 0.0f ? 1u : 0u) | (z0.y != 0.0f ? 2u : 0u) |
                    (z1.x != 0.0f ? 4u : 0u) | (z1.y != 0.0f ? 8u : 0u);
            }
            pre[nf] = p;
        }

        cp_wait<0>();
        __syncthreads();               // K/V[cur] landed; all warps done with cur^1

        if (jt + 1 < NA / 64) { loadK(cur ^ 1, jt + 1); loadV(cur ^ 1, jt + 1); cp_commit(); }

        const unsigned KsS = KbS + cur * (64 * 72) * 2;
        const unsigned VsS = VbS + cur * (64 * 72) * 2;

        // --- S = Q @ K^T + adj : K frags via ldmatrix.x4 (2 MMAs per load) ---
#pragma unroll
        for (int t = 0; t < 4; t++) {
#pragma unroll
            for (int nfp = 0; nfp < 4; nfp++) {
                unsigned bm[4];
                ldsm_x4(bm, KsS + (((nfp * 16 + kj) * 72) + t * 16 + kd) * 2);
                mma_f16(sa[2 * nfp],     qa[t], bm + 0);
                mma_f16(sa[2 * nfp + 1], qa[t], bm + 2);
            }
        }

        // --- mask ---
#pragma unroll
        for (int nf = 0; nf < 8; nf++) {
            unsigned p = pre[nf];
            if (p & 1u) sa[nf][0] = -1.0e30f;
            if (p & 2u) sa[nf][1] = -1.0e30f;
            if (p & 4u) sa[nf][2] = -1.0e30f;
            if (p & 8u) sa[nf][3] = -1.0e30f;
        }

        // --- online softmax (rows iG0, iG0+8) ---
        float mx0 = -3.0e38f, mx1 = -3.0e38f;
#pragma unroll
        for (int nf = 0; nf < 8; nf++) {
            mx0 = fmaxf(mx0, fmaxf(sa[nf][0], sa[nf][1]));
            mx1 = fmaxf(mx1, fmaxf(sa[nf][2], sa[nf][3]));
        }
        mx0 = fmaxf(mx0, __shfl_xor_sync(0xFFFFFFFFu, mx0, 1));
        mx0 = fmaxf(mx0, __shfl_xor_sync(0xFFFFFFFFu, mx0, 2));
        mx1 = fmaxf(mx1, __shfl_xor_sync(0xFFFFFFFFu, mx1, 1));
        mx1 = fmaxf(mx1, __shfl_xor_sync(0xFFFFFFFFu, mx1, 2));

        float mn0 = fmaxf(m0, mx0), mn1 = fmaxf(m1, mx1);
        float sc0 = __expf(m0 - mn0), sc1 = __expf(m1 - mn1);
        m0 = mn0; m1 = mn1;

        float p0 = 0.0f, p1 = 0.0f;
#pragma unroll
        for (int nf = 0; nf < 8; nf++) {
            sa[nf][0] = __expf(sa[nf][0] - mn0); p0 += sa[nf][0];
            sa[nf][1] = __expf(sa[nf][1] - mn0); p0 += sa[nf][1];
            sa[nf][2] = __expf(sa[nf][2] - mn1); p1 += sa[nf][2];
            sa[nf][3] = __expf(sa[nf][3] - mn1); p1 += sa[nf][3];
        }
        p0 += __shfl_xor_sync(0xFFFFFFFFu, p0, 1);
        p0 += __shfl_xor_sync(0xFFFFFFFFu, p0, 2);
        p1 += __shfl_xor_sync(0xFFFFFFFFu, p1, 1);
        p1 += __shfl_xor_sync(0xFFFFFFFFu, p1, 2);
        l0 = l0 * sc0 + p0;
        l1 = l1 * sc1 + p1;

#pragma unroll
        for (int nf = 0; nf < 8; nf++) {
            accO[nf][0] *= sc0; accO[nf][1] *= sc0;
            accO[nf][2] *= sc1; accO[nf][3] *= sc1;
        }

        // --- pack P accumulators -> fp16 A fragments (registers only) ---
        unsigned ph[8][2];
#pragma unroll
        for (int nf = 0; nf < 8; nf++) {
            ph[nf][0] = packh2(sa[nf][0], sa[nf][1]);   // row r
            ph[nf][1] = packh2(sa[nf][2], sa[nf][3]);   // row r+8
        }

        // --- PV: V frags via ldmatrix.x4.trans on raw [j][d] (2 MMAs per load) ---
#pragma unroll
        for (int t = 0; t < 4; t++) {
            unsigned pa[4] = { ph[2 * t][0], ph[2 * t][1],
                               ph[2 * t + 1][0], ph[2 * t + 1][1] };
#pragma unroll
            for (int nfp = 0; nfp < 4; nfp++) {
                unsigned bm[4];
                ldsm_x4_trans(bm, VsS + (((t * 16 + vj) * 72) + nfp * 16 + vd) * 2);
                mma_f16(accO[2 * nfp],     pa, bm + 0);
                mma_f16(accO[2 * nfp + 1], pa, bm + 2);
            }
        }
    }

    // --- epilogue: out = accO / l + x ---
    float li0 = 1.0f / l0, li1 = 1.0f / l1;
#pragma unroll
    for (int nf = 0; nf < 8; nf++) {
        int cG = h * 64 + nf * 8 + 2 * q;
        size_t o0 = ((size_t)(b * NA + iG0)) * C_DIM + cG;
        size_t o1 = ((size_t)(b * NA + iG0 + 8)) * C_DIM + cG;
        float2 x0 = *(const float2*)&x[o0];
        float2 x1 = *(const float2*)&x[o1];
        float2 r0 = { accO[nf][0] * li0 + x0.x, accO[nf][1] * li0 + x0.y };
        float2 r1 = { accO[nf][2] * li1 + x1.x, accO[nf][3] * li1 + x1.y };
        *(float2*)&out[o0] = r0;
        *(float2*)&out[o1] = r1;
    }
}

// ---------------- launch ----------------
#define SMEM_FLASH ((2 * 64 * 72 + 2 * 64 * 72) * 2)   // K(2) + V(2), fp16

extern "C" void kernel_launch(void* const* d_in, const int* in_sizes, int n_in,
                              void* d_out, int out_size) {
    const float* x    = (const float*)d_in[0];
    const void*  mask = d_in[1];
    const float* adj  = (const float*)d_in[2];
    const float* Wq   = (const float*)d_in[3];
    const float* Wk   = (const float*)d_in[4];
    const float* Wv   = (const float*)d_in[5];
    float* out = (float*)d_out;

    dim3 g1(NB * NA / 128, C_DIM / 128, 3);
    qkv_gemm_tc<<<g1, 256>>>(x, Wq, Wk, Wv, (const unsigned*)mask);

    cudaFuncSetAttribute(flash_tc, cudaFuncAttributeMaxDynamicSharedMemorySize, SMEM_FLASH);
    dim3 g2(NH, NA / 128, NB);
    flash_tc<<<g2, 256, SMEM_FLASH>>>(adj, mask, x, out);
}

// round 8
// speedup vs baseline: 5.6668x; 1.5248x over previous
#include <cuda_runtime.h>
#include <cuda_fp16.h>
#include <cstdint>
#include <cstddef>

#define NB 16
#define NA 1024
#define C_DIM 512
#define NH 8
#define D_DIM 64

// ---------------- device scratch ----------------
__device__ __half g_Qh[(size_t)NB * NH * NA * D_DIM];  // [b][h][i][d], pre-scaled by 1/TP
__device__ __half g_Kh[(size_t)NB * NH * NA * D_DIM];
__device__ __half g_Vh[(size_t)NB * NH * NA * D_DIM];
__device__ __half g_xh[(size_t)NB * NA * C_DIM];       // fp16 copy of x
__device__ __half g_Wqh[C_DIM * C_DIM];
__device__ __half g_Wkh[C_DIM * C_DIM];
__device__ __half g_Wvh[C_DIM * C_DIM];
__device__ float  g_adjm[(size_t)NB * NA * NA];        // adj with mask folded (-1e30)

// ---------------- helpers ----------------
static __device__ __forceinline__ void mma_f16(float* d, const unsigned* a,
                                               const unsigned* b) {
    asm volatile(
        "mma.sync.aligned.m16n8k16.row.col.f32.f16.f16.f32 "
        "{%0,%1,%2,%3}, {%4,%5,%6,%7}, {%8,%9}, {%0,%1,%2,%3};"
        : "+f"(d[0]), "+f"(d[1]), "+f"(d[2]), "+f"(d[3])
        : "r"(a[0]), "r"(a[1]), "r"(a[2]), "r"(a[3]),
          "r"(b[0]), "r"(b[1]));
}

static __device__ __forceinline__ void ldsm_x4(unsigned* d, unsigned saddr) {
    asm volatile(
        "ldmatrix.sync.aligned.m8n8.x4.shared.b16 {%0,%1,%2,%3}, [%4];"
        : "=r"(d[0]), "=r"(d[1]), "=r"(d[2]), "=r"(d[3]) : "r"(saddr));
}
static __device__ __forceinline__ void ldsm_x4_trans(unsigned* d, unsigned saddr) {
    asm volatile(
        "ldmatrix.sync.aligned.m8n8.x4.trans.shared.b16 {%0,%1,%2,%3}, [%4];"
        : "=r"(d[0]), "=r"(d[1]), "=r"(d[2]), "=r"(d[3]) : "r"(saddr));
}

static __device__ __forceinline__ unsigned packh2(float lo, float hi) {
    __half2 h = __floats2half2_rn(lo, hi);
    return *(unsigned*)&h;
}

static __device__ __forceinline__ void cp16(void* smem, const void* g) {
    unsigned saddr = (unsigned)__cvta_generic_to_shared(smem);
    asm volatile("cp.async.cg.shared.global [%0], [%1], 16;\n" :: "r"(saddr), "l"(g));
}
static __device__ __forceinline__ void cp_commit() {
    asm volatile("cp.async.commit_group;\n" ::: "memory");
}
template <int N>
static __device__ __forceinline__ void cp_wait() {
    asm volatile("cp.async.wait_group %0;\n" :: "n"(N) : "memory");
}

// ---------------- kernel 0: prep ----------------
// Converts x,W to fp16 and builds adjm = mask ? -1e30 : adj (mask dtype detected
// block-locally from the first 1KB of mask words; deterministic, L2-hot).
#define X_V4   ((size_t)NB * NA * C_DIM / 4)   // 2097152
#define W_V4   ((size_t)C_DIM * C_DIM / 4)     // 65536
#define ADJ_V4 ((size_t)NB * NA * NA / 4)      // 4194304

__global__ __launch_bounds__(256)
void prep_kernel(const float* __restrict__ x,
                 const float* __restrict__ Wq,
                 const float* __restrict__ Wk,
                 const float* __restrict__ Wv,
                 const float* __restrict__ adj,
                 const unsigned* __restrict__ mask) {
    __shared__ int s_mt;
    {
        unsigned v = mask[threadIdx.x];   // first 256 words of mask buffer
        int f32 = (v == 0x3F800000u);
        int gt1 = (!f32 && v > 1u);
        gt1 = __syncthreads_or(gt1);
        f32 = __syncthreads_or(f32);
        if (threadIdx.x == 0) s_mt = f32 ? 2 : (gt1 ? 0 : 1);  // 0=u8,1=i32,2=f32
        __syncthreads();
    }
    const int mt = s_mt;
    const size_t total = X_V4 + 3 * W_V4 + ADJ_V4;

    for (size_t u = (size_t)blockIdx.x * 256 + threadIdx.x; u < total;
         u += (size_t)gridDim.x * 256) {
        if (u < X_V4) {
            float4 v = ((const float4*)x)[u];
            ((__half2*)g_xh)[u * 2]     = __floats2half2_rn(v.x, v.y);
            ((__half2*)g_xh)[u * 2 + 1] = __floats2half2_rn(v.z, v.w);
        } else if (u < X_V4 + 3 * W_V4) {
            size_t t = u - X_V4;
            int wi = (int)(t / W_V4);
            size_t o = t % W_V4;
            const float4* Wsrc = (wi == 0) ? (const float4*)Wq
                               : (wi == 1) ? (const float4*)Wk : (const float4*)Wv;
            __half* dst = (wi == 0) ? g_Wqh : (wi == 1) ? g_Wkh : g_Wvh;
            float4 v = Wsrc[o];
            ((__half2*)dst)[o * 2]     = __floats2half2_rn(v.x, v.y);
            ((__half2*)dst)[o * 2 + 1] = __floats2half2_rn(v.z, v.w);
        } else {
            size_t o = u - X_V4 - 3 * W_V4;
            float4 a = ((const float4*)adj)[o];
            unsigned m0, m1, m2, m3;
            if (mt == 0) {
                unsigned w = mask[o];   // 4 packed u8 elements
                m0 = w & 0xFFu; m1 = w & 0xFF00u; m2 = w & 0xFF0000u; m3 = w & 0xFF000000u;
            } else {
                uint4 w = ((const uint4*)mask)[o];   // i32 or f32: nonzero = masked
                m0 = w.x; m1 = w.y; m2 = w.z; m3 = w.w;
            }
            if (m0) a.x = -1.0e30f;
            if (m1) a.y = -1.0e30f;
            if (m2) a.z = -1.0e30f;
            if (m3) a.w = -1.0e30f;
            ((float4*)g_adjm)[o] = a;
        }
    }
}

// ---------------- kernel 1: QKV projection (fp16 MMA + ldmatrix + cp.async) ----------------
// Y = xh(16384x512) @ Wh(512x512)^T -> fp16 [b][h][i][d]; Q pre-scaled by 1/TP.
// 256 thr = 8 warps (2m x 4n), block tile 128x128, BK=32, double-buffered.
__global__ __launch_bounds__(256, 2)
void qkv_gemm_f16() {
    __shared__ __half As[2][128 * 40];
    __shared__ __half Bs[2][128 * 40];

    const int z = blockIdx.z;
    const __half* __restrict__ Xs = g_xh;
    const __half* __restrict__ W = (z == 0) ? g_Wqh : (z == 1) ? g_Wkh : g_Wvh;
    __half* __restrict__ outp = (z == 0) ? g_Qh : (z == 1) ? g_Kh : g_Vh;

    const int mBase = blockIdx.x * 128;
    const int nBase = blockIdx.y * 128;
    const int tid = threadIdx.x;
    const int lane = tid & 31;
    const int warp = tid >> 5;
    const int q = lane & 3, r = lane >> 2;
    const int wm = warp & 1, wn = warp >> 1;

    const unsigned AsS = (unsigned)__cvta_generic_to_shared(&As[0][0]);
    const unsigned BsS = (unsigned)__cvta_generic_to_shared(&Bs[0][0]);

    // ldmatrix lane coords
    const int am = lane & 15, ac = (lane >> 4) * 8;                 // A frag
    const int kj = ((lane >> 4) & 1) * 8 + (lane & 7);              // B frag rows
    const int kd = ((lane >> 3) & 1) * 8;                           // B frag k half

    // tile 128 rows x 32 halves = 512 x 16B chunks / 256 thr = 2 each
    auto loadAB = [&](int buf, int k0) {
#pragma unroll
        for (int s = 0; s < 2; s++) {
            int slot = s * 256 + tid;
            int row = slot >> 2, ck = (slot & 3) * 8;
            cp16(&As[buf][row * 40 + ck], &Xs[(size_t)(mBase + row) * C_DIM + k0 + ck]);
            cp16(&Bs[buf][row * 40 + ck], &W[(size_t)(nBase + row) * C_DIM + k0 + ck]);
        }
    };

    float acc[4][4][4];
#pragma unroll
    for (int mf = 0; mf < 4; mf++)
#pragma unroll
        for (int nf = 0; nf < 4; nf++)
#pragma unroll
            for (int c = 0; c < 4; c++) acc[mf][nf][c] = 0.0f;

    loadAB(0, 0);
    cp_commit();

    for (int step = 0; step < 16; step++) {
        const int cur = step & 1;
        cp_wait<0>();
        __syncthreads();
        if (step < 15) { loadAB(cur ^ 1, (step + 1) * 32); cp_commit(); }

        const unsigned A = AsS + cur * (128 * 40) * 2;
        const unsigned B = BsS + cur * (128 * 40) * 2;
#pragma unroll
        for (int t = 0; t < 2; t++) {       // two k16 chunks in BK=32
            unsigned af[4][4];
#pragma unroll
            for (int mf = 0; mf < 4; mf++)
                ldsm_x4(af[mf], A + ((wm * 64 + mf * 16 + am) * 40 + t * 16 + ac) * 2);
#pragma unroll
            for (int nfp = 0; nfp < 2; nfp++) {
                unsigned bm[4];
                ldsm_x4(bm, B + ((wn * 32 + nfp * 16 + kj) * 40 + t * 16 + kd) * 2);
#pragma unroll
                for (int mf = 0; mf < 4; mf++) {
                    mma_f16(acc[mf][2 * nfp],     af[mf], bm + 0);
                    mma_f16(acc[mf][2 * nfp + 1], af[mf], bm + 2);
                }
            }
        }
    }

    const float sc = (z == 0) ? 0.08838834764831843f : 1.0f;  // 1/sqrt(2*64) into Q
#pragma unroll
    for (int mf = 0; mf < 4; mf++) {
        int mG = mBase + wm * 64 + mf * 16 + r;
#pragma unroll
        for (int nf = 0; nf < 4; nf++) {
            int nG = nBase + wn * 32 + nf * 8 + 2 * q;
            int h = nG >> 6, d = nG & 63;
            {
                int bb = mG >> 10, ii = mG & 1023;
                __half2 v = __floats2half2_rn(acc[mf][nf][0] * sc, acc[mf][nf][1] * sc);
                *(__half2*)&outp[(((size_t)(bb * NH + h) * NA + ii) * D_DIM) + d] = v;
            }
            {
                int mG2 = mG + 8;
                int bb = mG2 >> 10, ii = mG2 & 1023;
                __half2 v = __floats2half2_rn(acc[mf][nf][2] * sc, acc[mf][nf][3] * sc);
                *(__half2*)&outp[(((size_t)(bb * NH + h) * NA + ii) * D_DIM) + d] = v;
            }
        }
    }
}

// ---------------- kernel 2: fused flash attention (fp16, ldmatrix, adjm) ----------------
// grid (NH, NA/128, NB). 256 thr = 8 warps; warp w owns query rows w*16..+15.
// S = Q@K^T with adjm (mask pre-folded) seeded as MMA C. No mask logic at all.
__global__ __launch_bounds__(256, 2)
void flash_tc(const float* __restrict__ x, float* __restrict__ out) {
    extern __shared__ __half smh[];
    __half* Kb = smh;                    // 2 x 64*72 fp16
    __half* Vb = smh + 2 * 64 * 72;      // 2 x 64*72 fp16 (raw [j][d])

    const int h = blockIdx.x, iT = blockIdx.y, b = blockIdx.z;
    const int tid = threadIdx.x;
    const int lane = tid & 31;
    const int w = tid >> 5;
    const int q = lane & 3, r = lane >> 2;
    const int w16 = w * 16;
    const int bh = b * NH + h;

    const __half* __restrict__ Qp = g_Qh + (size_t)bh * NA * D_DIM;
    const __half* __restrict__ Kp = g_Kh + (size_t)bh * NA * D_DIM;
    const __half* __restrict__ Vp = g_Vh + (size_t)bh * NA * D_DIM;

    const unsigned KbS = (unsigned)__cvta_generic_to_shared(Kb);
    const unsigned VbS = (unsigned)__cvta_generic_to_shared(Vb);

    const int kj = ((lane >> 4) & 1) * 8 + (lane & 7);
    const int kd = ((lane >> 3) & 1) * 8;
    const int vj = ((lane >> 3) & 1) * 8 + (lane & 7);
    const int vd = ((lane >> 4) & 1) * 8;

    auto loadK = [&](int buf, int jt) {
        __half* Kd = Kb + buf * (64 * 72);
#pragma unroll
        for (int s = 0; s < 2; s++) {
            int slot = s * 256 + tid;
            int row = slot >> 3, ck = (slot & 7) * 8;
            cp16(&Kd[row * 72 + ck], &Kp[(size_t)(jt * 64 + row) * D_DIM + ck]);
        }
    };
    auto loadV = [&](int buf, int jt) {
        __half* Vd = Vb + buf * (64 * 72);
#pragma unroll
        for (int s = 0; s < 2; s++) {
            int slot = s * 256 + tid;
            int row = slot >> 3, ck = (slot & 7) * 8;
            cp16(&Vd[row * 72 + ck], &Vp[(size_t)(jt * 64 + row) * D_DIM + ck]);
        }
    };

    loadK(0, 0);
    loadV(0, 0);
    cp_commit();

    const int iG0 = iT * 128 + w16 + r;    // rows iG0 and iG0+8
    unsigned qa[4][4];
    {
        const __half* Q0 = Qp + (size_t)(iT * 128 + w16) * D_DIM;
#pragma unroll
        for (int t = 0; t < 4; t++) {
            qa[t][0] = *(const unsigned*)&Q0[(size_t)r * D_DIM + t * 16 + 2 * q];
            qa[t][1] = *(const unsigned*)&Q0[(size_t)(r + 8) * D_DIM + t * 16 + 2 * q];
            qa[t][2] = *(const unsigned*)&Q0[(size_t)r * D_DIM + t * 16 + 2 * q + 8];
            qa[t][3] = *(const unsigned*)&Q0[(size_t)(r + 8) * D_DIM + t * 16 + 2 * q + 8];
        }
    }

    float accO[8][4];
#pragma unroll
    for (int nf = 0; nf < 8; nf++)
#pragma unroll
        for (int c = 0; c < 4; c++) accO[nf][c] = 0.0f;

    float m0 = -3.0e38f, m1 = -3.0e38f, l0 = 0.0f, l1 = 0.0f;

    for (int jt = 0; jt < NA / 64; jt++) {
        const int cur = jt & 1;

        // ---- prefetch adjm straight into the S accumulators (MMA C-init) ----
        float sa[8][4];
#pragma unroll
        for (int nf = 0; nf < 8; nf++) {
            int jG = jt * 64 + nf * 8 + 2 * q;
            size_t o0 = ((size_t)b * NA + iG0) * NA + jG;
            float2 a0 = *(const float2*)&g_adjm[o0];
            float2 a1 = *(const float2*)&g_adjm[o0 + (size_t)8 * NA];
            sa[nf][0] = a0.x; sa[nf][1] = a0.y;
            sa[nf][2] = a1.x; sa[nf][3] = a1.y;
        }

        cp_wait<0>();
        __syncthreads();               // K/V[cur] landed; all warps done with cur^1

        if (jt + 1 < NA / 64) { loadK(cur ^ 1, jt + 1); loadV(cur ^ 1, jt + 1); cp_commit(); }

        const unsigned KsS = KbS + cur * (64 * 72) * 2;
        const unsigned VsS = VbS + cur * (64 * 72) * 2;

        // --- S = Q @ K^T + adjm ---
#pragma unroll
        for (int t = 0; t < 4; t++) {
#pragma unroll
            for (int nfp = 0; nfp < 4; nfp++) {
                unsigned bm[4];
                ldsm_x4(bm, KsS + (((nfp * 16 + kj) * 72) + t * 16 + kd) * 2);
                mma_f16(sa[2 * nfp],     qa[t], bm + 0);
                mma_f16(sa[2 * nfp + 1], qa[t], bm + 2);
            }
        }

        // --- online softmax (rows iG0, iG0+8) ---
        float mx0 = -3.0e38f, mx1 = -3.0e38f;
#pragma unroll
        for (int nf = 0; nf < 8; nf++) {
            mx0 = fmaxf(mx0, fmaxf(sa[nf][0], sa[nf][1]));
            mx1 = fmaxf(mx1, fmaxf(sa[nf][2], sa[nf][3]));
        }
        mx0 = fmaxf(mx0, __shfl_xor_sync(0xFFFFFFFFu, mx0, 1));
        mx0 = fmaxf(mx0, __shfl_xor_sync(0xFFFFFFFFu, mx0, 2));
        mx1 = fmaxf(mx1, __shfl_xor_sync(0xFFFFFFFFu, mx1, 1));
        mx1 = fmaxf(mx1, __shfl_xor_sync(0xFFFFFFFFu, mx1, 2));

        float mn0 = fmaxf(m0, mx0), mn1 = fmaxf(m1, mx1);
        float sc0 = __expf(m0 - mn0), sc1 = __expf(m1 - mn1);
        m0 = mn0; m1 = mn1;

        float p0 = 0.0f, p1 = 0.0f;
#pragma unroll
        for (int nf = 0; nf < 8; nf++) {
            sa[nf][0] = __expf(sa[nf][0] - mn0); p0 += sa[nf][0];
            sa[nf][1] = __expf(sa[nf][1] - mn0); p0 += sa[nf][1];
            sa[nf][2] = __expf(sa[nf][2] - mn1); p1 += sa[nf][2];
            sa[nf][3] = __expf(sa[nf][3] - mn1); p1 += sa[nf][3];
        }
        p0 += __shfl_xor_sync(0xFFFFFFFFu, p0, 1);
        p0 += __shfl_xor_sync(0xFFFFFFFFu, p0, 2);
        p1 += __shfl_xor_sync(0xFFFFFFFFu, p1, 1);
        p1 += __shfl_xor_sync(0xFFFFFFFFu, p1, 2);
        l0 = l0 * sc0 + p0;
        l1 = l1 * sc1 + p1;

#pragma unroll
        for (int nf = 0; nf < 8; nf++) {
            accO[nf][0] *= sc0; accO[nf][1] *= sc0;
            accO[nf][2] *= sc1; accO[nf][3] *= sc1;
        }

        // --- pack P -> fp16 A fragments (registers only) ---
        unsigned ph[8][2];
#pragma unroll
        for (int nf = 0; nf < 8; nf++) {
            ph[nf][0] = packh2(sa[nf][0], sa[nf][1]);
            ph[nf][1] = packh2(sa[nf][2], sa[nf][3]);
        }

        // --- PV: V frags via ldmatrix.x4.trans on raw [j][d] ---
#pragma unroll
        for (int t = 0; t < 4; t++) {
            unsigned pa[4] = { ph[2 * t][0], ph[2 * t][1],
                               ph[2 * t + 1][0], ph[2 * t + 1][1] };
#pragma unroll
            for (int nfp = 0; nfp < 4; nfp++) {
                unsigned bm[4];
                ldsm_x4_trans(bm, VsS + (((t * 16 + vj) * 72) + nfp * 16 + vd) * 2);
                mma_f16(accO[2 * nfp],     pa, bm + 0);
                mma_f16(accO[2 * nfp + 1], pa, bm + 2);
            }
        }
    }

    // --- epilogue: out = accO / l + x ---
    float li0 = 1.0f / l0, li1 = 1.0f / l1;
#pragma unroll
    for (int nf = 0; nf < 8; nf++) {
        int cG = h * 64 + nf * 8 + 2 * q;
        size_t o0 = ((size_t)(b * NA + iG0)) * C_DIM + cG;
        size_t o1 = ((size_t)(b * NA + iG0 + 8)) * C_DIM + cG;
        float2 x0 = *(const float2*)&x[o0];
        float2 x1 = *(const float2*)&x[o1];
        float2 r0 = { accO[nf][0] * li0 + x0.x, accO[nf][1] * li0 + x0.y };
        float2 r1 = { accO[nf][2] * li1 + x1.x, accO[nf][3] * li1 + x1.y };
        *(float2*)&out[o0] = r0;
        *(float2*)&out[o1] = r1;
    }
}

// ---------------- launch ----------------
#define SMEM_FLASH ((2 * 64 * 72 + 2 * 64 * 72) * 2)   // K(2) + V(2), fp16

extern "C" void kernel_launch(void* const* d_in, const int* in_sizes, int n_in,
                              void* d_out, int out_size) {
    const float* x    = (const float*)d_in[0];
    const void*  mask = d_in[1];
    const float* adj  = (const float*)d_in[2];
    const float* Wq   = (const float*)d_in[3];
    const float* Wk   = (const float*)d_in[4];
    const float* Wv   = (const float*)d_in[5];
    float* out = (float*)d_out;

    prep_kernel<<<4096, 256>>>(x, Wq, Wk, Wv, adj, (const unsigned*)mask);

    dim3 g1(NB * NA / 128, C_DIM / 128, 3);
    qkv_gemm_f16<<<g1, 256>>>();

    cudaFuncSetAttribute(flash_tc, cudaFuncAttributeMaxDynamicSharedMemorySize, SMEM_FLASH);
    dim3 g2(NH, NA / 128, NB);
    flash_tc<<<g2, 256, SMEM_FLASH>>>(x, out);
}

// round 9
// speedup vs baseline: 6.0520x; 1.0680x over previous
#include <cuda_runtime.h>
#include <cuda_fp16.h>
#include <cstdint>
#include <cstddef>

#define NB 16
#define NA 1024
#define C_DIM 512
#define NH 8
#define D_DIM 64

// ---------------- device scratch ----------------
__device__ __half g_Qh[(size_t)NB * NH * NA * D_DIM];  // [b][h][i][d], scaled by log2e/TP
__device__ __half g_Kh[(size_t)NB * NH * NA * D_DIM];
__device__ __half g_Vh[(size_t)NB * NH * NA * D_DIM];
__device__ __half g_xh[(size_t)NB * NA * C_DIM];       // fp16 copy of x
__device__ __half g_Wqh[C_DIM * C_DIM];
__device__ __half g_Wkh[C_DIM * C_DIM];
__device__ __half g_Wvh[C_DIM * C_DIM];
__device__ __half g_adjmh[(size_t)NB * NA * NA];       // adj*log2e, mask -> -30000 (fp16)

// ---------------- helpers ----------------
static __device__ __forceinline__ void mma_f16(float* d, const unsigned* a,
                                               const unsigned* b) {
    asm volatile(
        "mma.sync.aligned.m16n8k16.row.col.f32.f16.f16.f32 "
        "{%0,%1,%2,%3}, {%4,%5,%6,%7}, {%8,%9}, {%0,%1,%2,%3};"
        : "+f"(d[0]), "+f"(d[1]), "+f"(d[2]), "+f"(d[3])
        : "r"(a[0]), "r"(a[1]), "r"(a[2]), "r"(a[3]),
          "r"(b[0]), "r"(b[1]));
}

static __device__ __forceinline__ void ldsm_x4(unsigned* d, unsigned saddr) {
    asm volatile(
        "ldmatrix.sync.aligned.m8n8.x4.shared.b16 {%0,%1,%2,%3}, [%4];"
        : "=r"(d[0]), "=r"(d[1]), "=r"(d[2]), "=r"(d[3]) : "r"(saddr));
}
static __device__ __forceinline__ void ldsm_x4_trans(unsigned* d, unsigned saddr) {
    asm volatile(
        "ldmatrix.sync.aligned.m8n8.x4.trans.shared.b16 {%0,%1,%2,%3}, [%4];"
        : "=r"(d[0]), "=r"(d[1]), "=r"(d[2]), "=r"(d[3]) : "r"(saddr));
}

static __device__ __forceinline__ unsigned packh2(float lo, float hi) {
    __half2 h = __floats2half2_rn(lo, hi);
    return *(unsigned*)&h;
}

static __device__ __forceinline__ float ex2f(float x) {
    float y;
    asm("ex2.approx.ftz.f32 %0, %1;" : "=f"(y) : "f"(x));
    return y;
}

static __device__ __forceinline__ void cp16(void* smem, const void* g) {
    unsigned saddr = (unsigned)__cvta_generic_to_shared(smem);
    asm volatile("cp.async.cg.shared.global [%0], [%1], 16;\n" :: "r"(saddr), "l"(g));
}
static __device__ __forceinline__ void cp_commit() {
    asm volatile("cp.async.commit_group;\n" ::: "memory");
}
template <int N>
static __device__ __forceinline__ void cp_wait() {
    asm volatile("cp.async.wait_group %0;\n" :: "n"(N) : "memory");
}

// ---------------- kernel 0: prep ----------------
// x,W -> fp16; adjm = (mask ? -30000 : adj*log2e) in fp16. Mask dtype detected
// block-locally from the first 1KB of mask words (deterministic, L2-hot).
#define X_V4   ((size_t)NB * NA * C_DIM / 4)   // 2097152
#define W_V4   ((size_t)C_DIM * C_DIM / 4)     // 65536
#define ADJ_V4 ((size_t)NB * NA * NA / 4)      // 4194304

__global__ __launch_bounds__(256)
void prep_kernel(const float* __restrict__ x,
                 const float* __restrict__ Wq,
                 const float* __restrict__ Wk,
                 const float* __restrict__ Wv,
                 const float* __restrict__ adj,
                 const unsigned* __restrict__ mask) {
    __shared__ int s_mt;
    {
        unsigned v = mask[threadIdx.x];
        int f32 = (v == 0x3F800000u);
        int gt1 = (!f32 && v > 1u);
        gt1 = __syncthreads_or(gt1);
        f32 = __syncthreads_or(f32);
        if (threadIdx.x == 0) s_mt = f32 ? 2 : (gt1 ? 0 : 1);  // 0=u8,1=i32,2=f32
        __syncthreads();
    }
    const int mt = s_mt;
    const float L2E = 1.4426950408889634f;
    const size_t total = X_V4 + 3 * W_V4 + ADJ_V4;

    for (size_t u = (size_t)blockIdx.x * 256 + threadIdx.x; u < total;
         u += (size_t)gridDim.x * 256) {
        if (u < X_V4) {
            float4 v = ((const float4*)x)[u];
            ((__half2*)g_xh)[u * 2]     = __floats2half2_rn(v.x, v.y);
            ((__half2*)g_xh)[u * 2 + 1] = __floats2half2_rn(v.z, v.w);
        } else if (u < X_V4 + 3 * W_V4) {
            size_t t = u - X_V4;
            int wi = (int)(t / W_V4);
            size_t o = t % W_V4;
            const float4* Wsrc = (wi == 0) ? (const float4*)Wq
                               : (wi == 1) ? (const float4*)Wk : (const float4*)Wv;
            __half* dst = (wi == 0) ? g_Wqh : (wi == 1) ? g_Wkh : g_Wvh;
            float4 v = Wsrc[o];
            ((__half2*)dst)[o * 2]     = __floats2half2_rn(v.x, v.y);
            ((__half2*)dst)[o * 2 + 1] = __floats2half2_rn(v.z, v.w);
        } else {
            size_t o = u - X_V4 - 3 * W_V4;
            float4 a = ((const float4*)adj)[o];
            a.x *= L2E; a.y *= L2E; a.z *= L2E; a.w *= L2E;
            unsigned m0, m1, m2, m3;
            if (mt == 0) {
                unsigned w = mask[o];   // 4 packed u8 elements
                m0 = w & 0xFFu; m1 = w & 0xFF00u; m2 = w & 0xFF0000u; m3 = w & 0xFF000000u;
            } else {
                uint4 w = ((const uint4*)mask)[o];   // i32 or f32: nonzero = masked
                m0 = w.x; m1 = w.y; m2 = w.z; m3 = w.w;
            }
            if (m0) a.x = -30000.0f;
            if (m1) a.y = -30000.0f;
            if (m2) a.z = -30000.0f;
            if (m3) a.w = -30000.0f;
            ((__half2*)g_adjmh)[o * 2]     = __floats2half2_rn(a.x, a.y);
            ((__half2*)g_adjmh)[o * 2 + 1] = __floats2half2_rn(a.z, a.w);
        }
    }
}

// ---------------- kernel 1: QKV projection (fp16 MMA + ldmatrix + cp.async) ----------------
// Y = xh(16384x512) @ Wh(512x512)^T -> fp16 [b][h][i][d]; Q scaled by log2e/TP.
__global__ __launch_bounds__(256, 2)
void qkv_gemm_f16() {
    __shared__ __half As[2][128 * 40];
    __shared__ __half Bs[2][128 * 40];

    const int z = blockIdx.z;
    const __half* __restrict__ Xs = g_xh;
    const __half* __restrict__ W = (z == 0) ? g_Wqh : (z == 1) ? g_Wkh : g_Wvh;
    __half* __restrict__ outp = (z == 0) ? g_Qh : (z == 1) ? g_Kh : g_Vh;

    const int mBase = blockIdx.x * 128;
    const int nBase = blockIdx.y * 128;
    const int tid = threadIdx.x;
    const int lane = tid & 31;
    const int warp = tid >> 5;
    const int q = lane & 3, r = lane >> 2;
    const int wm = warp & 1, wn = warp >> 1;

    const unsigned AsS = (unsigned)__cvta_generic_to_shared(&As[0][0]);
    const unsigned BsS = (unsigned)__cvta_generic_to_shared(&Bs[0][0]);

    const int am = lane & 15, ac = (lane >> 4) * 8;
    const int kj = ((lane >> 4) & 1) * 8 + (lane & 7);
    const int kd = ((lane >> 3) & 1) * 8;

    auto loadAB = [&](int buf, int k0) {
#pragma unroll
        for (int s = 0; s < 2; s++) {
            int slot = s * 256 + tid;
            int row = slot >> 2, ck = (slot & 3) * 8;
            cp16(&As[buf][row * 40 + ck], &Xs[(size_t)(mBase + row) * C_DIM + k0 + ck]);
            cp16(&Bs[buf][row * 40 + ck], &W[(size_t)(nBase + row) * C_DIM + k0 + ck]);
        }
    };

    float acc[4][4][4];
#pragma unroll
    for (int mf = 0; mf < 4; mf++)
#pragma unroll
        for (int nf = 0; nf < 4; nf++)
#pragma unroll
            for (int c = 0; c < 4; c++) acc[mf][nf][c] = 0.0f;

    loadAB(0, 0);
    cp_commit();

    for (int step = 0; step < 16; step++) {
        const int cur = step & 1;
        cp_wait<0>();
        __syncthreads();
        if (step < 15) { loadAB(cur ^ 1, (step + 1) * 32); cp_commit(); }

        const unsigned A = AsS + cur * (128 * 40) * 2;
        const unsigned B = BsS + cur * (128 * 40) * 2;
#pragma unroll
        for (int t = 0; t < 2; t++) {
            unsigned af[4][4];
#pragma unroll
            for (int mf = 0; mf < 4; mf++)
                ldsm_x4(af[mf], A + ((wm * 64 + mf * 16 + am) * 40 + t * 16 + ac) * 2);
#pragma unroll
            for (int nfp = 0; nfp < 2; nfp++) {
                unsigned bm[4];
                ldsm_x4(bm, B + ((wn * 32 + nfp * 16 + kj) * 40 + t * 16 + kd) * 2);
#pragma unroll
                for (int mf = 0; mf < 4; mf++) {
                    mma_f16(acc[mf][2 * nfp],     af[mf], bm + 0);
                    mma_f16(acc[mf][2 * nfp + 1], af[mf], bm + 2);
                }
            }
        }
    }

    // Q scale = log2e / sqrt(2*64); K,V unscaled
    const float sc = (z == 0) ? 0.12751744416986734f : 1.0f;
#pragma unroll
    for (int mf = 0; mf < 4; mf++) {
        int mG = mBase + wm * 64 + mf * 16 + r;
#pragma unroll
        for (int nf = 0; nf < 4; nf++) {
            int nG = nBase + wn * 32 + nf * 8 + 2 * q;
            int h = nG >> 6, d = nG & 63;
            {
                int bb = mG >> 10, ii = mG & 1023;
                __half2 v = __floats2half2_rn(acc[mf][nf][0] * sc, acc[mf][nf][1] * sc);
                *(__half2*)&outp[(((size_t)(bb * NH + h) * NA + ii) * D_DIM) + d] = v;
            }
            {
                int mG2 = mG + 8;
                int bb = mG2 >> 10, ii = mG2 & 1023;
                __half2 v = __floats2half2_rn(acc[mf][nf][2] * sc, acc[mf][nf][3] * sc);
                *(__half2*)&outp[(((size_t)(bb * NH + h) * NA + ii) * D_DIM) + d] = v;
            }
        }
    }
}

// ---------------- kernel 2: fused flash attention (fp16, log2-domain softmax) ----------------
// grid (NH, NA/128, NB). 256 thr = 8 warps; warp w owns query rows w*16..+15.
// Scores are in log2 domain (log2e folded into Q and adjm) -> bare ex2, no FMUL.
__global__ __launch_bounds__(256, 2)
void flash_tc(const float* __restrict__ x, float* __restrict__ out) {
    extern __shared__ __half smh[];
    __half* Kb = smh;                    // 2 x 64*72 fp16
    __half* Vb = smh + 2 * 64 * 72;      // 2 x 64*72 fp16 (raw [j][d])

    const int h = blockIdx.x, iT = blockIdx.y, b = blockIdx.z;
    const int tid = threadIdx.x;
    const int lane = tid & 31;
    const int w = tid >> 5;
    const int q = lane & 3, r = lane >> 2;
    const int w16 = w * 16;
    const int bh = b * NH + h;

    const __half* __restrict__ Qp = g_Qh + (size_t)bh * NA * D_DIM;
    const __half* __restrict__ Kp = g_Kh + (size_t)bh * NA * D_DIM;
    const __half* __restrict__ Vp = g_Vh + (size_t)bh * NA * D_DIM;

    const unsigned KbS = (unsigned)__cvta_generic_to_shared(Kb);
    const unsigned VbS = (unsigned)__cvta_generic_to_shared(Vb);

    const int kj = ((lane >> 4) & 1) * 8 + (lane & 7);
    const int kd = ((lane >> 3) & 1) * 8;
    const int vj = ((lane >> 3) & 1) * 8 + (lane & 7);
    const int vd = ((lane >> 4) & 1) * 8;

    auto loadK = [&](int buf, int jt) {
        __half* Kd = Kb + buf * (64 * 72);
#pragma unroll
        for (int s = 0; s < 2; s++) {
            int slot = s * 256 + tid;
            int row = slot >> 3, ck = (slot & 7) * 8;
            cp16(&Kd[row * 72 + ck], &Kp[(size_t)(jt * 64 + row) * D_DIM + ck]);
        }
    };
    auto loadV = [&](int buf, int jt) {
        __half* Vd = Vb + buf * (64 * 72);
#pragma unroll
        for (int s = 0; s < 2; s++) {
            int slot = s * 256 + tid;
            int row = slot >> 3, ck = (slot & 7) * 8;
            cp16(&Vd[row * 72 + ck], &Vp[(size_t)(jt * 64 + row) * D_DIM + ck]);
        }
    };

    loadK(0, 0);
    loadV(0, 0);
    cp_commit();

    const int iG0 = iT * 128 + w16 + r;    // rows iG0 and iG0+8
    unsigned qa[4][4];
    {
        const __half* Q0 = Qp + (size_t)(iT * 128 + w16) * D_DIM;
#pragma unroll
        for (int t = 0; t < 4; t++) {
            qa[t][0] = *(const unsigned*)&Q0[(size_t)r * D_DIM + t * 16 + 2 * q];
            qa[t][1] = *(const unsigned*)&Q0[(size_t)(r + 8) * D_DIM + t * 16 + 2 * q];
            qa[t][2] = *(const unsigned*)&Q0[(size_t)r * D_DIM + t * 16 + 2 * q + 8];
            qa[t][3] = *(const unsigned*)&Q0[(size_t)(r + 8) * D_DIM + t * 16 + 2 * q + 8];
        }
    }

    float accO[8][4];
#pragma unroll
    for (int nf = 0; nf < 8; nf++)
#pragma unroll
        for (int c = 0; c < 4; c++) accO[nf][c] = 0.0f;

    float m0 = -3.0e38f, m1 = -3.0e38f, l0 = 0.0f, l1 = 0.0f;

    for (int jt = 0; jt < NA / 64; jt++) {
        const int cur = jt & 1;

        // ---- prefetch fp16 adjm straight into the S accumulators (MMA C-init) ----
        float sa[8][4];
#pragma unroll
        for (int nf = 0; nf < 8; nf++) {
            int jG = jt * 64 + nf * 8 + 2 * q;
            size_t o0 = ((size_t)b * NA + iG0) * NA + jG;
            __half2 a0 = *(const __half2*)&g_adjmh[o0];
            __half2 a1 = *(const __half2*)&g_adjmh[o0 + (size_t)8 * NA];
            float2 f0 = __half22float2(a0);
            float2 f1 = __half22float2(a1);
            sa[nf][0] = f0.x; sa[nf][1] = f0.y;
            sa[nf][2] = f1.x; sa[nf][3] = f1.y;
        }

        cp_wait<0>();
        __syncthreads();               // K/V[cur] landed; all warps done with cur^1

        if (jt + 1 < NA / 64) { loadK(cur ^ 1, jt + 1); loadV(cur ^ 1, jt + 1); cp_commit(); }

        const unsigned KsS = KbS + cur * (64 * 72) * 2;
        const unsigned VsS = VbS + cur * (64 * 72) * 2;

        // --- S = Q @ K^T + adjm (log2 domain) ---
#pragma unroll
        for (int t = 0; t < 4; t++) {
#pragma unroll
            for (int nfp = 0; nfp < 4; nfp++) {
                unsigned bm[4];
                ldsm_x4(bm, KsS + (((nfp * 16 + kj) * 72) + t * 16 + kd) * 2);
                mma_f16(sa[2 * nfp],     qa[t], bm + 0);
                mma_f16(sa[2 * nfp + 1], qa[t], bm + 2);
            }
        }

        // --- online softmax in log2 domain (rows iG0, iG0+8) ---
        float mx0 = -3.0e38f, mx1 = -3.0e38f;
#pragma unroll
        for (int nf = 0; nf < 8; nf++) {
            mx0 = fmaxf(mx0, fmaxf(sa[nf][0], sa[nf][1]));
            mx1 = fmaxf(mx1, fmaxf(sa[nf][2], sa[nf][3]));
        }
        mx0 = fmaxf(mx0, __shfl_xor_sync(0xFFFFFFFFu, mx0, 1));
        mx0 = fmaxf(mx0, __shfl_xor_sync(0xFFFFFFFFu, mx0, 2));
        mx1 = fmaxf(mx1, __shfl_xor_sync(0xFFFFFFFFu, mx1, 1));
        mx1 = fmaxf(mx1, __shfl_xor_sync(0xFFFFFFFFu, mx1, 2));

        float mn0 = fmaxf(m0, mx0), mn1 = fmaxf(m1, mx1);
        float sc0 = ex2f(m0 - mn0), sc1 = ex2f(m1 - mn1);
        m0 = mn0; m1 = mn1;

        float p0 = 0.0f, p1 = 0.0f;
#pragma unroll
        for (int nf = 0; nf < 8; nf++) {
            sa[nf][0] = ex2f(sa[nf][0] - mn0); p0 += sa[nf][0];
            sa[nf][1] = ex2f(sa[nf][1] - mn0); p0 += sa[nf][1];
            sa[nf][2] = ex2f(sa[nf][2] - mn1); p1 += sa[nf][2];
            sa[nf][3] = ex2f(sa[nf][3] - mn1); p1 += sa[nf][3];
        }
        p0 += __shfl_xor_sync(0xFFFFFFFFu, p0, 1);
        p0 += __shfl_xor_sync(0xFFFFFFFFu, p0, 2);
        p1 += __shfl_xor_sync(0xFFFFFFFFu, p1, 1);
        p1 += __shfl_xor_sync(0xFFFFFFFFu, p1, 2);
        l0 = l0 * sc0 + p0;
        l1 = l1 * sc1 + p1;

#pragma unroll
        for (int nf = 0; nf < 8; nf++) {
            accO[nf][0] *= sc0; accO[nf][1] *= sc0;
            accO[nf][2] *= sc1; accO[nf][3] *= sc1;
        }

        // --- pack P -> fp16 A fragments (registers only) ---
        unsigned ph[8][2];
#pragma unroll
        for (int nf = 0; nf < 8; nf++) {
            ph[nf][0] = packh2(sa[nf][0], sa[nf][1]);
            ph[nf][1] = packh2(sa[nf][2], sa[nf][3]);
        }

        // --- PV: V frags via ldmatrix.x4.trans on raw [j][d] ---
#pragma unroll
        for (int t = 0; t < 4; t++) {
            unsigned pa[4] = { ph[2 * t][0], ph[2 * t][1],
                               ph[2 * t + 1][0], ph[2 * t + 1][1] };
#pragma unroll
            for (int nfp = 0; nfp < 4; nfp++) {
                unsigned bm[4];
                ldsm_x4_trans(bm, VsS + (((t * 16 + vj) * 72) + nfp * 16 + vd) * 2);
                mma_f16(accO[2 * nfp],     pa, bm + 0);
                mma_f16(accO[2 * nfp + 1], pa, bm + 2);
            }
        }
    }

    // --- epilogue: out = accO / l + x ---
    float li0 = 1.0f / l0, li1 = 1.0f / l1;
#pragma unroll
    for (int nf = 0; nf < 8; nf++) {
        int cG = h * 64 + nf * 8 + 2 * q;
        size_t o0 = ((size_t)(b * NA + iG0)) * C_DIM + cG;
        size_t o1 = ((size_t)(b * NA + iG0 + 8)) * C_DIM + cG;
        float2 x0 = *(const float2*)&x[o0];
        float2 x1 = *(const float2*)&x[o1];
        float2 r0 = { accO[nf][0] * li0 + x0.x, accO[nf][1] * li0 + x0.y };
        float2 r1 = { accO[nf][2] * li1 + x1.x, accO[nf][3] * li1 + x1.y };
        *(float2*)&out[o0] = r0;
        *(float2*)&out[o1] = r1;
    }
}

// ---------------- launch ----------------
#define SMEM_FLASH ((2 * 64 * 72 + 2 * 64 * 72) * 2)   // K(2) + V(2), fp16

extern "C" void kernel_launch(void* const* d_in, const int* in_sizes, int n_in,
                              void* d_out, int out_size) {
    const float* x    = (const float*)d_in[0];
    const void*  mask = d_in[1];
    const float* adj  = (const float*)d_in[2];
    const float* Wq   = (const float*)d_in[3];
    const float* Wk   = (const float*)d_in[4];
    const float* Wv   = (const float*)d_in[5];
    float* out = (float*)d_out;

    prep_kernel<<<4096, 256>>>(x, Wq, Wk, Wv, adj, (const unsigned*)mask);

    dim3 g1(NB * NA / 128, C_DIM / 128, 3);
    qkv_gemm_f16<<<g1, 256>>>();

    cudaFuncSetAttribute(flash_tc, cudaFuncAttributeMaxDynamicSharedMemorySize, SMEM_FLASH);
    dim3 g2(NH, NA / 128, NB);
    flash_tc<<<g2, 256, SMEM_FLASH>>>(x, out);
}

// round 10
// speedup vs baseline: 6.4430x; 1.0646x over previous
#include <cuda_runtime.h>
#include <cuda_fp16.h>
#include <cstdint>
#include <cstddef>

#define NB 16
#define NA 1024
#define C_DIM 512
#define NH 8
#define D_DIM 64

// ---------------- device scratch ----------------
__device__ __half g_Qh[(size_t)NB * NH * NA * D_DIM];  // [b][h][i][d], scaled by log2e/TP
__device__ __half g_Kh[(size_t)NB * NH * NA * D_DIM];
__device__ __half g_Vh[(size_t)NB * NH * NA * D_DIM];
__device__ __half g_xh[(size_t)NB * NA * C_DIM];       // fp16 copy of x
__device__ __half g_Wqh[C_DIM * C_DIM];
__device__ __half g_Wkh[C_DIM * C_DIM];
__device__ __half g_Wvh[C_DIM * C_DIM];
__device__ __half g_adjmh[(size_t)NB * NA * NA];       // adj*log2e, mask -> -30000 (fp16)

// ---------------- helpers ----------------
static __device__ __forceinline__ void mma_f16(float* d, const unsigned* a,
                                               const unsigned* b) {
    asm volatile(
        "mma.sync.aligned.m16n8k16.row.col.f32.f16.f16.f32 "
        "{%0,%1,%2,%3}, {%4,%5,%6,%7}, {%8,%9}, {%0,%1,%2,%3};"
        : "+f"(d[0]), "+f"(d[1]), "+f"(d[2]), "+f"(d[3])
        : "r"(a[0]), "r"(a[1]), "r"(a[2]), "r"(a[3]),
          "r"(b[0]), "r"(b[1]));
}

static __device__ __forceinline__ void ldsm_x4(unsigned* d, unsigned saddr) {
    asm volatile(
        "ldmatrix.sync.aligned.m8n8.x4.shared.b16 {%0,%1,%2,%3}, [%4];"
        : "=r"(d[0]), "=r"(d[1]), "=r"(d[2]), "=r"(d[3]) : "r"(saddr));
}
static __device__ __forceinline__ void ldsm_x4_trans(unsigned* d, unsigned saddr) {
    asm volatile(
        "ldmatrix.sync.aligned.m8n8.x4.trans.shared.b16 {%0,%1,%2,%3}, [%4];"
        : "=r"(d[0]), "=r"(d[1]), "=r"(d[2]), "=r"(d[3]) : "r"(saddr));
}

static __device__ __forceinline__ unsigned packh2(float lo, float hi) {
    __half2 h = __floats2half2_rn(lo, hi);
    return *(unsigned*)&h;
}

static __device__ __forceinline__ float ex2f(float x) {
    float y;
    asm("ex2.approx.ftz.f32 %0, %1;" : "=f"(y) : "f"(x));
    return y;
}

static __device__ __forceinline__ void cp16(void* smem, const void* g) {
    unsigned saddr = (unsigned)__cvta_generic_to_shared(smem);
    asm volatile("cp.async.cg.shared.global [%0], [%1], 16;\n" :: "r"(saddr), "l"(g));
}
static __device__ __forceinline__ void cp_commit() {
    asm volatile("cp.async.commit_group;\n" ::: "memory");
}
template <int N>
static __device__ __forceinline__ void cp_wait() {
    asm volatile("cp.async.wait_group %0;\n" :: "n"(N) : "memory");
}

// ---------------- kernel 0: prep ----------------
#define X_V4   ((size_t)NB * NA * C_DIM / 4)   // 2097152
#define W_V4   ((size_t)C_DIM * C_DIM / 4)     // 65536
#define ADJ_V4 ((size_t)NB * NA * NA / 4)      // 4194304

__global__ __launch_bounds__(256)
void prep_kernel(const float* __restrict__ x,
                 const float* __restrict__ Wq,
                 const float* __restrict__ Wk,
                 const float* __restrict__ Wv,
                 const float* __restrict__ adj,
                 const unsigned* __restrict__ mask) {
    __shared__ int s_mt;
    {
        unsigned v = mask[threadIdx.x];
        int f32 = (v == 0x3F800000u);
        int gt1 = (!f32 && v > 1u);
        gt1 = __syncthreads_or(gt1);
        f32 = __syncthreads_or(f32);
        if (threadIdx.x == 0) s_mt = f32 ? 2 : (gt1 ? 0 : 1);  // 0=u8,1=i32,2=f32
        __syncthreads();
    }
    const int mt = s_mt;
    const float L2E = 1.4426950408889634f;
    const size_t total = X_V4 + 3 * W_V4 + ADJ_V4;

    for (size_t u = (size_t)blockIdx.x * 256 + threadIdx.x; u < total;
         u += (size_t)gridDim.x * 256) {
        if (u < X_V4) {
            float4 v = ((const float4*)x)[u];
            ((__half2*)g_xh)[u * 2]     = __floats2half2_rn(v.x, v.y);
            ((__half2*)g_xh)[u * 2 + 1] = __floats2half2_rn(v.z, v.w);
        } else if (u < X_V4 + 3 * W_V4) {
            size_t t = u - X_V4;
            int wi = (int)(t / W_V4);
            size_t o = t % W_V4;
            const float4* Wsrc = (wi == 0) ? (const float4*)Wq
                               : (wi == 1) ? (const float4*)Wk : (const float4*)Wv;
            __half* dst = (wi == 0) ? g_Wqh : (wi == 1) ? g_Wkh : g_Wvh;
            float4 v = Wsrc[o];
            ((__half2*)dst)[o * 2]     = __floats2half2_rn(v.x, v.y);
            ((__half2*)dst)[o * 2 + 1] = __floats2half2_rn(v.z, v.w);
        } else {
            size_t o = u - X_V4 - 3 * W_V4;
            float4 a = ((const float4*)adj)[o];
            a.x *= L2E; a.y *= L2E; a.z *= L2E; a.w *= L2E;
            unsigned m0, m1, m2, m3;
            if (mt == 0) {
                unsigned w = mask[o];   // 4 packed u8 elements
                m0 = w & 0xFFu; m1 = w & 0xFF00u; m2 = w & 0xFF0000u; m3 = w & 0xFF000000u;
            } else {
                uint4 w = ((const uint4*)mask)[o];   // i32 or f32: nonzero = masked
                m0 = w.x; m1 = w.y; m2 = w.z; m3 = w.w;
            }
            if (m0) a.x = -30000.0f;
            if (m1) a.y = -30000.0f;
            if (m2) a.z = -30000.0f;
            if (m3) a.w = -30000.0f;
            ((__half2*)g_adjmh)[o * 2]     = __floats2half2_rn(a.x, a.y);
            ((__half2*)g_adjmh)[o * 2 + 1] = __floats2half2_rn(a.z, a.w);
        }
    }
}

// ---------------- kernel 1: QKV projection (fp16 MMA + ldmatrix + cp.async) ----------------
__global__ __launch_bounds__(256, 2)
void qkv_gemm_f16() {
    __shared__ __half As[2][128 * 40];
    __shared__ __half Bs[2][128 * 40];

    const int z = blockIdx.z;
    const __half* __restrict__ Xs = g_xh;
    const __half* __restrict__ W = (z == 0) ? g_Wqh : (z == 1) ? g_Wkh : g_Wvh;
    __half* __restrict__ outp = (z == 0) ? g_Qh : (z == 1) ? g_Kh : g_Vh;

    const int mBase = blockIdx.x * 128;
    const int nBase = blockIdx.y * 128;
    const int tid = threadIdx.x;
    const int lane = tid & 31;
    const int warp = tid >> 5;
    const int q = lane & 3, r = lane >> 2;
    const int wm = warp & 1, wn = warp >> 1;

    const unsigned AsS = (unsigned)__cvta_generic_to_shared(&As[0][0]);
    const unsigned BsS = (unsigned)__cvta_generic_to_shared(&Bs[0][0]);

    const int am = lane & 15, ac = (lane >> 4) * 8;
    const int kj = ((lane >> 4) & 1) * 8 + (lane & 7);
    const int kd = ((lane >> 3) & 1) * 8;

    auto loadAB = [&](int buf, int k0) {
#pragma unroll
        for (int s = 0; s < 2; s++) {
            int slot = s * 256 + tid;
            int row = slot >> 2, ck = (slot & 3) * 8;
            cp16(&As[buf][row * 40 + ck], &Xs[(size_t)(mBase + row) * C_DIM + k0 + ck]);
            cp16(&Bs[buf][row * 40 + ck], &W[(size_t)(nBase + row) * C_DIM + k0 + ck]);
        }
    };

    float acc[4][4][4];
#pragma unroll
    for (int mf = 0; mf < 4; mf++)
#pragma unroll
        for (int nf = 0; nf < 4; nf++)
#pragma unroll
            for (int c = 0; c < 4; c++) acc[mf][nf][c] = 0.0f;

    loadAB(0, 0);
    cp_commit();

    for (int step = 0; step < 16; step++) {
        const int cur = step & 1;
        cp_wait<0>();
        __syncthreads();
        if (step < 15) { loadAB(cur ^ 1, (step + 1) * 32); cp_commit(); }

        const unsigned A = AsS + cur * (128 * 40) * 2;
        const unsigned B = BsS + cur * (128 * 40) * 2;
#pragma unroll
        for (int t = 0; t < 2; t++) {
            unsigned af[4][4];
#pragma unroll
            for (int mf = 0; mf < 4; mf++)
                ldsm_x4(af[mf], A + ((wm * 64 + mf * 16 + am) * 40 + t * 16 + ac) * 2);
#pragma unroll
            for (int nfp = 0; nfp < 2; nfp++) {
                unsigned bm[4];
                ldsm_x4(bm, B + ((wn * 32 + nfp * 16 + kj) * 40 + t * 16 + kd) * 2);
#pragma unroll
                for (int mf = 0; mf < 4; mf++) {
                    mma_f16(acc[mf][2 * nfp],     af[mf], bm + 0);
                    mma_f16(acc[mf][2 * nfp + 1], af[mf], bm + 2);
                }
            }
        }
    }

    // Q scale = log2e / sqrt(2*64); K,V unscaled
    const float sc = (z == 0) ? 0.12751744416986734f : 1.0f;
#pragma unroll
    for (int mf = 0; mf < 4; mf++) {
        int mG = mBase + wm * 64 + mf * 16 + r;
#pragma unroll
        for (int nf = 0; nf < 4; nf++) {
            int nG = nBase + wn * 32 + nf * 8 + 2 * q;
            int h = nG >> 6, d = nG & 63;
            {
                int bb = mG >> 10, ii = mG & 1023;
                __half2 v = __floats2half2_rn(acc[mf][nf][0] * sc, acc[mf][nf][1] * sc);
                *(__half2*)&outp[(((size_t)(bb * NH + h) * NA + ii) * D_DIM) + d] = v;
            }
            {
                int mG2 = mG + 8;
                int bb = mG2 >> 10, ii = mG2 & 1023;
                __half2 v = __floats2half2_rn(acc[mf][nf][2] * sc, acc[mf][nf][3] * sc);
                *(__half2*)&outp[(((size_t)(bb * NH + h) * NA + ii) * D_DIM) + d] = v;
            }
        }
    }
}

// ---------------- kernel 2: fused flash attention ----------------
// grid (NH, NA/128, NB). 256 thr = 8 warps; warp w owns query rows w*16..+15.
// adjm tile (128x64 fp16) cp.async-staged and fragmented via ldmatrix.x4 at
// stride 72 (conflict-free) -> the scattered adj LDGs are gone entirely.
// K/V/adj all double-buffered in one commit group; log2-domain softmax.
#define KV_BUF  (64 * 72)     // halves per K or V buffer
#define ADJ_BUF (128 * 72)    // halves per adj buffer

__global__ __launch_bounds__(256, 2)
void flash_tc(const float* __restrict__ x, float* __restrict__ out) {
    extern __shared__ __half smh[];
    __half* Kb = smh;                        // 2 x KV_BUF
    __half* Vb = smh + 2 * KV_BUF;           // 2 x KV_BUF
    __half* Ab = smh + 4 * KV_BUF;           // 2 x ADJ_BUF

    const int h = blockIdx.x, iT = blockIdx.y, b = blockIdx.z;
    const int tid = threadIdx.x;
    const int lane = tid & 31;
    const int w = tid >> 5;
    const int q = lane & 3, r = lane >> 2;
    const int w16 = w * 16;
    const int bh = b * NH + h;

    const __half* __restrict__ Qp = g_Qh + (size_t)bh * NA * D_DIM;
    const __half* __restrict__ Kp = g_Kh + (size_t)bh * NA * D_DIM;
    const __half* __restrict__ Vp = g_Vh + (size_t)bh * NA * D_DIM;
    const __half* __restrict__ Ap = g_adjmh + ((size_t)b * NA + iT * 128) * NA;

    const unsigned KbS = (unsigned)__cvta_generic_to_shared(Kb);
    const unsigned VbS = (unsigned)__cvta_generic_to_shared(Vb);
    const unsigned AbS = (unsigned)__cvta_generic_to_shared(Ab);

    const int kj = ((lane >> 4) & 1) * 8 + (lane & 7);
    const int kd = ((lane >> 3) & 1) * 8;
    const int vj = ((lane >> 3) & 1) * 8 + (lane & 7);
    const int vd = ((lane >> 4) & 1) * 8;
    const int arow = w16 + (lane & 15);          // adj ldmatrix row
    const int acol = ((lane >> 4) & 1) * 8;      // adj ldmatrix col half

    auto loadKV = [&](int buf, int jt) {
        __half* Kd = Kb + buf * KV_BUF;
        __half* Vd = Vb + buf * KV_BUF;
#pragma unroll
        for (int s = 0; s < 2; s++) {
            int slot = s * 256 + tid;
            int row = slot >> 3, ck = (slot & 7) * 8;
            cp16(&Kd[row * 72 + ck], &Kp[(size_t)(jt * 64 + row) * D_DIM + ck]);
            cp16(&Vd[row * 72 + ck], &Vp[(size_t)(jt * 64 + row) * D_DIM + ck]);
        }
    };
    auto loadAdj = [&](int buf, int jt) {
        __half* Ad = Ab + buf * ADJ_BUF;
#pragma unroll
        for (int s = 0; s < 4; s++) {
            int slot = s * 256 + tid;
            int row = slot >> 3, ck = (slot & 7) * 8;   // row 0..127, ck 0..56
            cp16(&Ad[row * 72 + ck], &Ap[(size_t)row * NA + jt * 64 + ck]);
        }
    };

    loadKV(0, 0);
    loadAdj(0, 0);
    cp_commit();

    const int iG0 = iT * 128 + w16 + r;    // rows iG0 and iG0+8
    unsigned qa[4][4];
    {
        const __half* Q0 = Qp + (size_t)(iT * 128 + w16) * D_DIM;
#pragma unroll
        for (int t = 0; t < 4; t++) {
            qa[t][0] = *(const unsigned*)&Q0[(size_t)r * D_DIM + t * 16 + 2 * q];
            qa[t][1] = *(const unsigned*)&Q0[(size_t)(r + 8) * D_DIM + t * 16 + 2 * q];
            qa[t][2] = *(const unsigned*)&Q0[(size_t)r * D_DIM + t * 16 + 2 * q + 8];
            qa[t][3] = *(const unsigned*)&Q0[(size_t)(r + 8) * D_DIM + t * 16 + 2 * q + 8];
        }
    }

    float accO[8][4];
#pragma unroll
    for (int nf = 0; nf < 8; nf++)
#pragma unroll
        for (int c = 0; c < 4; c++) accO[nf][c] = 0.0f;

    float m0 = -3.0e38f, m1 = -3.0e38f, l0 = 0.0f, l1 = 0.0f;

    for (int jt = 0; jt < NA / 64; jt++) {
        const int cur = jt & 1;

        cp_wait<0>();
        __syncthreads();               // K/V/adj[cur] landed; all warps done with cur^1

        if (jt + 1 < NA / 64) {
            loadKV(cur ^ 1, jt + 1);
            loadAdj(cur ^ 1, jt + 1);
            cp_commit();
        }

        const unsigned KsS = KbS + cur * KV_BUF * 2;
        const unsigned VsS = VbS + cur * KV_BUF * 2;
        const unsigned AsS = AbS + cur * ADJ_BUF * 2;

        // --- adj fragments via ldmatrix.x4 -> seed S accumulators ---
        float sa[8][4];
#pragma unroll
        for (int nfp = 0; nfp < 4; nfp++) {
            unsigned am[4];
            ldsm_x4(am, AsS + (arow * 72 + nfp * 16 + acol) * 2);
            float2 f0 = __half22float2(*(__half2*)&am[0]);
            float2 f1 = __half22float2(*(__half2*)&am[1]);
            float2 f2 = __half22float2(*(__half2*)&am[2]);
            float2 f3 = __half22float2(*(__half2*)&am[3]);
            sa[2 * nfp][0] = f0.x;     sa[2 * nfp][1] = f0.y;
            sa[2 * nfp][2] = f1.x;     sa[2 * nfp][3] = f1.y;
            sa[2 * nfp + 1][0] = f2.x; sa[2 * nfp + 1][1] = f2.y;
            sa[2 * nfp + 1][2] = f3.x; sa[2 * nfp + 1][3] = f3.y;
        }

        // --- S = Q @ K^T + adjm (log2 domain) ---
#pragma unroll
        for (int t = 0; t < 4; t++) {
#pragma unroll
            for (int nfp = 0; nfp < 4; nfp++) {
                unsigned bm[4];
                ldsm_x4(bm, KsS + (((nfp * 16 + kj) * 72) + t * 16 + kd) * 2);
                mma_f16(sa[2 * nfp],     qa[t], bm + 0);
                mma_f16(sa[2 * nfp + 1], qa[t], bm + 2);
            }
        }

        // --- online softmax in log2 domain (rows iG0, iG0+8) ---
        float mx0 = -3.0e38f, mx1 = -3.0e38f;
#pragma unroll
        for (int nf = 0; nf < 8; nf++) {
            mx0 = fmaxf(mx0, fmaxf(sa[nf][0], sa[nf][1]));
            mx1 = fmaxf(mx1, fmaxf(sa[nf][2], sa[nf][3]));
        }
        mx0 = fmaxf(mx0, __shfl_xor_sync(0xFFFFFFFFu, mx0, 1));
        mx0 = fmaxf(mx0, __shfl_xor_sync(0xFFFFFFFFu, mx0, 2));
        mx1 = fmaxf(mx1, __shfl_xor_sync(0xFFFFFFFFu, mx1, 1));
        mx1 = fmaxf(mx1, __shfl_xor_sync(0xFFFFFFFFu, mx1, 2));

        float mn0 = fmaxf(m0, mx0), mn1 = fmaxf(m1, mx1);
        float sc0 = ex2f(m0 - mn0), sc1 = ex2f(m1 - mn1);
        m0 = mn0; m1 = mn1;

        float p0 = 0.0f, p1 = 0.0f;
#pragma unroll
        for (int nf = 0; nf < 8; nf++) {
            sa[nf][0] = ex2f(sa[nf][0] - mn0); p0 += sa[nf][0];
            sa[nf][1] = ex2f(sa[nf][1] - mn0); p0 += sa[nf][1];
            sa[nf][2] = ex2f(sa[nf][2] - mn1); p1 += sa[nf][2];
            sa[nf][3] = ex2f(sa[nf][3] - mn1); p1 += sa[nf][3];
        }
        p0 += __shfl_xor_sync(0xFFFFFFFFu, p0, 1);
        p0 += __shfl_xor_sync(0xFFFFFFFFu, p0, 2);
        p1 += __shfl_xor_sync(0xFFFFFFFFu, p1, 1);
        p1 += __shfl_xor_sync(0xFFFFFFFFu, p1, 2);
        l0 = l0 * sc0 + p0;
        l1 = l1 * sc1 + p1;

#pragma unroll
        for (int nf = 0; nf < 8; nf++) {
            accO[nf][0] *= sc0; accO[nf][1] *= sc0;
            accO[nf][2] *= sc1; accO[nf][3] *= sc1;
        }

        // --- pack P -> fp16 A fragments (registers only) ---
        unsigned ph[8][2];
#pragma unroll
        for (int nf = 0; nf < 8; nf++) {
            ph[nf][0] = packh2(sa[nf][0], sa[nf][1]);
            ph[nf][1] = packh2(sa[nf][2], sa[nf][3]);
        }

        // --- PV: V frags via ldmatrix.x4.trans on raw [j][d] ---
#pragma unroll
        for (int t = 0; t < 4; t++) {
            unsigned pa[4] = { ph[2 * t][0], ph[2 * t][1],
                               ph[2 * t + 1][0], ph[2 * t + 1][1] };
#pragma unroll
            for (int nfp = 0; nfp < 4; nfp++) {
                unsigned bm[4];
                ldsm_x4_trans(bm, VsS + (((t * 16 + vj) * 72) + nfp * 16 + vd) * 2);
                mma_f16(accO[2 * nfp],     pa, bm + 0);
                mma_f16(accO[2 * nfp + 1], pa, bm + 2);
            }
        }
    }

    // --- epilogue: out = accO / l + x ---
    float li0 = 1.0f / l0, li1 = 1.0f / l1;
#pragma unroll
    for (int nf = 0; nf < 8; nf++) {
        int cG = h * 64 + nf * 8 + 2 * q;
        size_t o0 = ((size_t)(b * NA + iG0)) * C_DIM + cG;
        size_t o1 = ((size_t)(b * NA + iG0 + 8)) * C_DIM + cG;
        float2 x0 = *(const float2*)&x[o0];
        float2 x1 = *(const float2*)&x[o1];
        float2 r0 = { accO[nf][0] * li0 + x0.x, accO[nf][1] * li0 + x0.y };
        float2 r1 = { accO[nf][2] * li1 + x1.x, accO[nf][3] * li1 + x1.y };
        *(float2*)&out[o0] = r0;
        *(float2*)&out[o1] = r1;
    }
}

// ---------------- launch ----------------
#define SMEM_FLASH ((4 * KV_BUF + 2 * ADJ_BUF) * 2)   // K(2)+V(2)+adj(2), fp16 = 73728 B

extern "C" void kernel_launch(void* const* d_in, const int* in_sizes, int n_in,
                              void* d_out, int out_size) {
    const float* x    = (const float*)d_in[0];
    const void*  mask = d_in[1];
    const float* adj  = (const float*)d_in[2];
    const float* Wq   = (const float*)d_in[3];
    const float* Wk   = (const float*)d_in[4];
    const float* Wv   = (const float*)d_in[5];
    float* out = (float*)d_out;

    prep_kernel<<<4096, 256>>>(x, Wq, Wk, Wv, adj, (const unsigned*)mask);

    dim3 g1(NB * NA / 128, C_DIM / 128, 3);
    qkv_gemm_f16<<<g1, 256>>>();

    cudaFuncSetAttribute(flash_tc, cudaFuncAttributeMaxDynamicSharedMemorySize, SMEM_FLASH);
    dim3 g2(NH, NA / 128, NB);
    flash_tc<<<g2, 256, SMEM_FLASH>>>(x, out);
}